// round 1
// baseline (speedup 1.0000x reference)
#include <cuda_runtime.h>
#include <math.h>

#define C_ 256
#define G_ 16
#define CPG 16
#define N_ 8
#define H_ 80
#define W_ 80
#define HW 6400
#define CHW (C_*HW)
#define NCHW (N_*C_*HW)
#define EPSV 1e-5f

// Scratch (static device globals; no runtime allocation)
__device__ float g_buf1[NCHW];
__device__ float g_buf2[NCHW];
__device__ float g_buf3[NCHW];
__device__ float g_rowsum[N_*C_*H_];
__device__ float g_colsum[N_*C_*W_];
__device__ float g_stats1[N_*G_*2];
__device__ float g_stats2[N_*G_*2];

// ---------------------------------------------------------------------------
// GEMM: Y[n, o, hw] = sum_c Wm[o,c] * X[n, c, hw]
// Wm: [256,256] row-major.  X/Y: [N, C, HW].
// Tiles: BM=BN=128, BK=16. 256 threads, 8x8 microtile per thread.
// grid: (HW/128, 256/128, N) = (50, 2, 8)
// ---------------------------------------------------------------------------
__global__ __launch_bounds__(256, 2)
void gemm_k(const float* __restrict__ Wm, const float* __restrict__ X,
            float* __restrict__ Y) {
    __shared__ float As[16][132];
    __shared__ float Bs[16][128];

    const int tid = threadIdx.x;
    const float* Xn = X + (size_t)blockIdx.z * CHW;
    float* Yn = Y + (size_t)blockIdx.z * CHW;
    const int col0 = blockIdx.x * 128;
    const int row0 = blockIdx.y * 128;

    const int tx = tid & 15;   // col group
    const int ty = tid >> 4;   // row group

    float acc[8][8];
#pragma unroll
    for (int i = 0; i < 8; i++)
#pragma unroll
        for (int j = 0; j < 8; j++) acc[i][j] = 0.f;

    for (int k0 = 0; k0 < 256; k0 += 16) {
        // Load A tile (128 rows x 16 k), store transposed
#pragma unroll
        for (int r = 0; r < 2; r++) {
            int i = tid + 256 * r;        // float4 index 0..511
            int m = i >> 2;               // 0..127
            int kq = (i & 3) * 4;         // 0,4,8,12
            float4 v = *(const float4*)(Wm + (size_t)(row0 + m) * 256 + k0 + kq);
            As[kq + 0][m] = v.x;
            As[kq + 1][m] = v.y;
            As[kq + 2][m] = v.z;
            As[kq + 3][m] = v.w;
        }
        // Load B tile (16 k x 128 cols)
#pragma unroll
        for (int r = 0; r < 2; r++) {
            int i = tid + 256 * r;        // float4 index 0..511
            int kk = i >> 5;              // 0..15
            int nn = (i & 31) * 4;        // 0..124
            *(float4*)(&Bs[kk][nn]) =
                *(const float4*)(Xn + (size_t)(k0 + kk) * HW + col0 + nn);
        }
        __syncthreads();

        float ar[8], br[8];
#pragma unroll
        for (int k = 0; k < 16; k++) {
            *(float4*)(ar)     = *(float4*)(&As[k][ty * 8]);
            *(float4*)(ar + 4) = *(float4*)(&As[k][ty * 8 + 4]);
            *(float4*)(br)     = *(float4*)(&Bs[k][tx * 8]);
            *(float4*)(br + 4) = *(float4*)(&Bs[k][tx * 8 + 4]);
#pragma unroll
            for (int i = 0; i < 8; i++)
#pragma unroll
                for (int j = 0; j < 8; j++)
                    acc[i][j] += ar[i] * br[j];
        }
        __syncthreads();
    }

#pragma unroll
    for (int i = 0; i < 8; i++) {
        int m = row0 + ty * 8 + i;
        float* yp = Yn + (size_t)m * HW + col0 + tx * 8;
        *(float4*)(yp)     = make_float4(acc[i][0], acc[i][1], acc[i][2], acc[i][3]);
        *(float4*)(yp + 4) = make_float4(acc[i][4], acc[i][5], acc[i][6], acc[i][7]);
    }
}

// ---------------------------------------------------------------------------
// GroupNorm stats: per (n,g) mean & rstd over contiguous span of CPG*HW floats
// grid: N*G blocks, 256 threads
// ---------------------------------------------------------------------------
__global__ void gn_stats_k(const float* __restrict__ X, float* __restrict__ stats) {
    const int ng = blockIdx.x;
    const float* p = X + (size_t)ng * (CPG * HW);
    const int M = CPG * HW;  // 102400
    float s = 0.f, s2 = 0.f;
    for (int i = threadIdx.x * 4; i < M; i += blockDim.x * 4) {
        float4 v = *(const float4*)(p + i);
        s  += v.x + v.y + v.z + v.w;
        s2 += v.x * v.x + v.y * v.y + v.z * v.z + v.w * v.w;
    }
    __shared__ float sA[256], sB[256];
    sA[threadIdx.x] = s;
    sB[threadIdx.x] = s2;
    __syncthreads();
    for (int off = 128; off > 0; off >>= 1) {
        if (threadIdx.x < off) {
            sA[threadIdx.x] += sA[threadIdx.x + off];
            sB[threadIdx.x] += sB[threadIdx.x + off];
        }
        __syncthreads();
    }
    if (threadIdx.x == 0) {
        float mean = sA[0] / (float)M;
        float var  = sB[0] / (float)M - mean * mean;
        stats[ng * 2]     = mean;
        stats[ng * 2 + 1] = rsqrtf(var + EPSV);
    }
}

// ---------------------------------------------------------------------------
// GN + SiLU (in-place) + row/col sums.  One block per (n,c) plane.
// grid: N*C blocks, 256 threads
// ---------------------------------------------------------------------------
__global__ void gn_silu_rowcol_k(float* __restrict__ X,
                                 const float* __restrict__ stats,
                                 const float* __restrict__ gamma,
                                 const float* __restrict__ beta,
                                 float* __restrict__ rowsum,
                                 float* __restrict__ colsum) {
    __shared__ float plane[HW];
    const int nc = blockIdx.x;
    const int c = nc & (C_ - 1);
    const int ng = (nc >> 8) * G_ + (c >> 4);
    const float mean = stats[ng * 2];
    const float rstd = stats[ng * 2 + 1];
    const float ga = gamma[c];
    const float be = beta[c];
    float* base = X + (size_t)nc * HW;

    for (int i = threadIdx.x; i < HW; i += 256) {
        float v = base[i];
        v = (v - mean) * rstd * ga + be;
        float sg = 1.f / (1.f + expf(-v));
        v = v * sg;
        plane[i] = v;
        base[i] = v;
    }
    __syncthreads();
    if (threadIdx.x < H_) {
        const int y = threadIdx.x;
        float s = 0.f;
        for (int x = 0; x < W_; x++) s += plane[y * W_ + x];
        rowsum[nc * H_ + y] = s;
    } else if (threadIdx.x < H_ + W_) {
        const int x = threadIdx.x - H_;
        float s = 0.f;
        for (int y = 0; y < H_; y++) s += plane[y * W_ + x];
        colsum[nc * W_ + x] = s;
    }
}

// ---------------------------------------------------------------------------
// gated = 0.25*(rowsum[y] + colsum[x] + 2*h) * sigmoid(gate0 + b_gate[c])
// ---------------------------------------------------------------------------
__global__ void gated_k(const float* __restrict__ h,
                        const float* __restrict__ gate0,
                        const float* __restrict__ rowsum,
                        const float* __restrict__ colsum,
                        const float* __restrict__ b_gate,
                        float* __restrict__ out) {
    const int idx = blockIdx.x * 256 + threadIdx.x;
    const int nc = idx / HW;
    const int hw = idx - nc * HW;
    const int y = hw / W_;
    const int x = hw - y * W_;
    const int c = nc & (C_ - 1);
    float fused = 0.25f * (rowsum[nc * H_ + y] + colsum[nc * W_ + x] + 2.f * h[idx]);
    float gz = gate0[idx] + b_gate[c];
    float gate = 1.f / (1.f + expf(-gz));
    out[idx] = fused * gate;
}

// ---------------------------------------------------------------------------
// depthwise 3x3, padding 1
// ---------------------------------------------------------------------------
__global__ void dw3x3_k(const float* __restrict__ in,
                        const float* __restrict__ wdw,
                        float* __restrict__ out) {
    const int idx = blockIdx.x * 256 + threadIdx.x;
    const int nc = idx / HW;
    const int hw = idx - nc * HW;
    const int y = hw / W_;
    const int x = hw - y * W_;
    const int c = nc & (C_ - 1);
    const float* w = wdw + c * 9;
    const float* p = in + (size_t)nc * HW;
    float s = 0.f;
#pragma unroll
    for (int dy = -1; dy <= 1; dy++) {
        int yy = y + dy;
        if ((unsigned)yy >= H_) continue;
#pragma unroll
        for (int dx = -1; dx <= 1; dx++) {
            int xx = x + dx;
            if ((unsigned)xx >= W_) continue;
            s += w[(dy + 1) * 3 + (dx + 1)] * __ldg(p + yy * W_ + xx);
        }
    }
    out[idx] = s;
}

// ---------------------------------------------------------------------------
// final: out = silu(gn(y))
// ---------------------------------------------------------------------------
__global__ void gn_silu_out_k(const float* __restrict__ X,
                              const float* __restrict__ stats,
                              const float* __restrict__ gamma,
                              const float* __restrict__ beta,
                              float* __restrict__ out) {
    const int idx = blockIdx.x * 256 + threadIdx.x;
    const int nc = idx / HW;
    const int c = nc & (C_ - 1);
    const int ng = (nc >> 8) * G_ + (c >> 4);
    float v = X[idx];
    v = (v - stats[ng * 2]) * stats[ng * 2 + 1] * gamma[c] + beta[c];
    float sg = 1.f / (1.f + expf(-v));
    out[idx] = v * sg;
}

// ---------------------------------------------------------------------------
extern "C" void kernel_launch(void* const* d_in, const int* in_sizes, int n_in,
                              void* d_out, int out_size) {
    const float* x      = (const float*)d_in[0];
    const float* w_pre  = (const float*)d_in[1];
    const float* g1     = (const float*)d_in[2];
    const float* b1     = (const float*)d_in[3];
    const float* w_gate = (const float*)d_in[4];
    const float* b_gate = (const float*)d_in[5];
    const float* w_dw   = (const float*)d_in[6];
    const float* w_pw   = (const float*)d_in[7];
    const float* g2     = (const float*)d_in[8];
    const float* b2     = (const float*)d_in[9];
    float* out = (float*)d_out;

    float *buf1, *buf2, *buf3, *rowsum, *colsum, *stats1, *stats2;
    cudaGetSymbolAddress((void**)&buf1, g_buf1);
    cudaGetSymbolAddress((void**)&buf2, g_buf2);
    cudaGetSymbolAddress((void**)&buf3, g_buf3);
    cudaGetSymbolAddress((void**)&rowsum, g_rowsum);
    cudaGetSymbolAddress((void**)&colsum, g_colsum);
    cudaGetSymbolAddress((void**)&stats1, g_stats1);
    cudaGetSymbolAddress((void**)&stats2, g_stats2);

    dim3 ggrid(HW / 128, C_ / 128, N_);
    const int eblocks = NCHW / 256;

    // 1) h0 = conv1x1(x, w_pre)
    gemm_k<<<ggrid, 256>>>(w_pre, x, buf1);
    // 2) GN1 stats
    gn_stats_k<<<N_ * G_, 256>>>(buf1, stats1);
    // 3) h = silu(gn(h0)) in-place + row/col sums
    gn_silu_rowcol_k<<<N_ * C_, 256>>>(buf1, stats1, g1, b1, rowsum, colsum);
    // 4) gate0 = conv1x1(h, w_gate)
    gemm_k<<<ggrid, 256>>>(w_gate, buf1, buf2);
    // 5) gated
    gated_k<<<eblocks, 256>>>(buf1, buf2, rowsum, colsum, b_gate, buf3);
    // 6) depthwise 3x3
    dw3x3_k<<<eblocks, 256>>>(buf3, w_dw, buf2);
    // 7) y = conv1x1(dw, w_pw)
    gemm_k<<<ggrid, 256>>>(w_pw, buf2, buf1);
    // 8) GN2 stats
    gn_stats_k<<<N_ * G_, 256>>>(buf1, stats2);
    // 9) out = silu(gn(y))
    gn_silu_out_k<<<eblocks, 256>>>(buf1, stats2, g2, b2, out);
}

// round 3
// speedup vs baseline: 1.6131x; 1.6131x over previous
#include <cuda_runtime.h>
#include <cuda_bf16.h>
#include <math.h>
#include <cstdint>

#define C_ 256
#define G_ 16
#define CPG 16
#define N_ 8
#define H_ 80
#define W_ 80
#define HW 6400
#define CHW (C_*HW)
#define NCHW (N_*C_*HW)
#define EPSV 1e-5f

// Scratch (static device globals; no runtime allocation)
__device__ float g_buf1[NCHW];
__device__ float g_buf2[NCHW];
__device__ float g_buf3[NCHW];
__device__ float g_rowsum[N_*C_*H_];
__device__ float g_colsum[N_*C_*W_];
__device__ float g_stats1[N_*G_*2];
__device__ float g_stats2[N_*G_*2];

__device__ __forceinline__ uint32_t smem_u32(const void* p) {
    uint32_t a;
    asm("{ .reg .u64 t; cvta.to.shared.u64 t, %1; cvt.u32.u64 %0, t; }"
        : "=r"(a) : "l"(p));
    return a;
}

// ===========================================================================
// bf16 split-precision tensor-core GEMM (mma.sync — compiles at compute_103)
// Y[n, o, hw] = sum_c Wm[o,c] * X[n, c, hw]
// CTA tile M=128 (o), N=128 (hw), K-chunk 32, double-buffered.
// 8 warps: 2 (m) x 4 (n); warp tile 64x32; mma m16n8k16 bf16.
// Split: acc += Ahi*Bhi + Ahi*Blo + Alo*Bhi  (fp32 accum)
// smem per stage: Ahi[128][40]bf16 | Alo | Bhi[32][136]bf16 | Blo = 37888 B
// ===========================================================================
#define A_STRIDE 40      // bf16 elems per A row (32 + 8 pad) -> 80 B
#define B_STRIDE 136     // bf16 elems per B row (128 + 8 pad) -> 272 B
#define OFF_ALO  10240
#define OFF_BHI  20480
#define OFF_BLO  29184
#define STAGE_B  37888
#define GEMM_SMEM (2*STAGE_B)

__device__ __forceinline__ void ldsm_x4(uint32_t* r, uint32_t addr) {
    asm volatile("ldmatrix.sync.aligned.m8n8.x4.shared.b16 {%0,%1,%2,%3}, [%4];"
        : "=r"(r[0]), "=r"(r[1]), "=r"(r[2]), "=r"(r[3]) : "r"(addr));
}
__device__ __forceinline__ void ldsm_x2t(uint32_t* r, uint32_t addr) {
    asm volatile("ldmatrix.sync.aligned.m8n8.x2.trans.shared.b16 {%0,%1}, [%2];"
        : "=r"(r[0]), "=r"(r[1]) : "r"(addr));
}
__device__ __forceinline__ void mma_bf16(float* c, const uint32_t* a, const uint32_t* b) {
    asm volatile(
        "mma.sync.aligned.m16n8k16.row.col.f32.bf16.bf16.f32 "
        "{%0,%1,%2,%3}, {%4,%5,%6,%7}, {%8,%9}, {%0,%1,%2,%3};"
        : "+f"(c[0]), "+f"(c[1]), "+f"(c[2]), "+f"(c[3])
        : "r"(a[0]), "r"(a[1]), "r"(a[2]), "r"(a[3]), "r"(b[0]), "r"(b[1]));
}

__device__ __forceinline__ void cvt_split4(const float4& v, uint32_t& hi01, uint32_t& hi23,
                                           uint32_t& lo01, uint32_t& lo23) {
    __nv_bfloat16 hx = __float2bfloat16(v.x), hy = __float2bfloat16(v.y);
    __nv_bfloat16 hz = __float2bfloat16(v.z), hw = __float2bfloat16(v.w);
    __nv_bfloat162 h01(hx, hy), h23(hz, hw);
    __nv_bfloat162 l01(__float2bfloat16(v.x - __bfloat162float(hx)),
                       __float2bfloat16(v.y - __bfloat162float(hy)));
    __nv_bfloat162 l23(__float2bfloat16(v.z - __bfloat162float(hz)),
                       __float2bfloat16(v.w - __bfloat162float(hw)));
    hi01 = *(uint32_t*)&h01; hi23 = *(uint32_t*)&h23;
    lo01 = *(uint32_t*)&l01; lo23 = *(uint32_t*)&l23;
}

__global__ __launch_bounds__(256, 1)
void gemm_mma(const float* __restrict__ Wm, const float* __restrict__ X,
              float* __restrict__ Y) {
    extern __shared__ char smem[];
    const uint32_t sb = smem_u32(smem);
    const int tid = threadIdx.x;
    const int lane = tid & 31;
    const int w = tid >> 5;
    const int wm = w & 1;        // 0..1  (64-row group)
    const int wn = w >> 1;       // 0..3  (32-col group)
    const int n0 = blockIdx.x * 128;
    const int m0 = blockIdx.y * 128;
    const float* Xn = X + (size_t)blockIdx.z * CHW;
    float* Yn = Y + (size_t)blockIdx.z * CHW;

    float acc[4][4][4];
#pragma unroll
    for (int i = 0; i < 4; i++)
#pragma unroll
        for (int j = 0; j < 4; j++)
#pragma unroll
            for (int q = 0; q < 4; q++) acc[i][j][q] = 0.f;

    // staging registers
    float4 ra[4], rb[4];

    // ---- load chunk 0 ----
#pragma unroll
    for (int j = 0; j < 4; j++) {
        int idx = tid + 256 * j;                  // A: 1024 float4s
        int m = idx >> 3, kq = (idx & 7) * 4;
        ra[j] = *(const float4*)(Wm + (size_t)(m0 + m) * 256 + kq);
        int kk = idx >> 5, nq = (idx & 31) * 4;   // B: 1024 float4s
        rb[j] = *(const float4*)(Xn + (size_t)kk * HW + n0 + nq);
    }
    // store chunk 0 into stage 0
    {
        char* base = smem;
#pragma unroll
        for (int j = 0; j < 4; j++) {
            int idx = tid + 256 * j;
            int m = idx >> 3, kq = (idx & 7) * 4;
            uint32_t h01, h23, l01, l23;
            cvt_split4(ra[j], h01, h23, l01, l23);
            uint32_t off = (uint32_t)(m * A_STRIDE + kq) * 2;
            *(uint32_t*)(base + off) = h01; *(uint32_t*)(base + off + 4) = h23;
            *(uint32_t*)(base + OFF_ALO + off) = l01; *(uint32_t*)(base + OFF_ALO + off + 4) = l23;
            int kk = idx >> 5, nq = (idx & 31) * 4;
            cvt_split4(rb[j], h01, h23, l01, l23);
            uint32_t boff = (uint32_t)(kk * B_STRIDE + nq) * 2;
            *(uint32_t*)(base + OFF_BHI + boff) = h01; *(uint32_t*)(base + OFF_BHI + boff + 4) = h23;
            *(uint32_t*)(base + OFF_BLO + boff) = l01; *(uint32_t*)(base + OFF_BLO + boff + 4) = l23;
        }
    }
    __syncthreads();

    const uint32_t a_lane_off = (uint32_t)((lane & 15) * A_STRIDE + ((lane >> 4) << 3)) * 2;
    const uint32_t b_lane_off = (uint32_t)((lane & 15) * B_STRIDE) * 2;

    for (int ch = 0; ch < 8; ch++) {
        const int st = ch & 1;
        // prefetch next chunk
        if (ch < 7) {
            const int k0 = (ch + 1) * 32;
#pragma unroll
            for (int j = 0; j < 4; j++) {
                int idx = tid + 256 * j;
                int m = idx >> 3, kq = (idx & 7) * 4;
                ra[j] = *(const float4*)(Wm + (size_t)(m0 + m) * 256 + k0 + kq);
                int kk = idx >> 5, nq = (idx & 31) * 4;
                rb[j] = *(const float4*)(Xn + (size_t)(k0 + kk) * HW + n0 + nq);
            }
        }
        // compute on stage st
        {
            const uint32_t SB = sb + st * STAGE_B;
            const uint32_t a_base = SB + (uint32_t)(wm * 64) * (A_STRIDE * 2) + a_lane_off;
            const uint32_t b_base = SB + OFF_BHI + (uint32_t)(wn * 32 + (lane & 15) * 0) * 2 + b_lane_off
                                    + (uint32_t)(wn * 32) * 0;  // col added below
#pragma unroll
            for (int ks = 0; ks < 2; ks++) {
                const uint32_t kb = (uint32_t)(ks * 16);
                uint32_t ah[4][4], al[4][4], bh[4][2], bl[4][2];
#pragma unroll
                for (int mt = 0; mt < 4; mt++) {
                    uint32_t ad = a_base + (uint32_t)(mt * 16) * (A_STRIDE * 2) + kb * 2;
                    ldsm_x4(ah[mt], ad);
                    ldsm_x4(al[mt], ad + OFF_ALO);
                }
#pragma unroll
                for (int nt = 0; nt < 4; nt++) {
                    uint32_t bd = SB + OFF_BHI + b_lane_off + kb * (B_STRIDE * 2)
                                  + (uint32_t)(wn * 32 + nt * 8) * 2;
                    ldsm_x2t(bh[nt], bd);
                    ldsm_x2t(bl[nt], bd + (OFF_BLO - OFF_BHI));
                }
#pragma unroll
                for (int mt = 0; mt < 4; mt++)
#pragma unroll
                    for (int nt = 0; nt < 4; nt++) {
                        mma_bf16(acc[mt][nt], ah[mt], bh[nt]);
                        mma_bf16(acc[mt][nt], ah[mt], bl[nt]);
                        mma_bf16(acc[mt][nt], al[mt], bh[nt]);
                    }
            }
        }
        // store next chunk to other stage
        if (ch < 7) {
            char* base = smem + ((ch + 1) & 1) * STAGE_B;
#pragma unroll
            for (int j = 0; j < 4; j++) {
                int idx = tid + 256 * j;
                int m = idx >> 3, kq = (idx & 7) * 4;
                uint32_t h01, h23, l01, l23;
                cvt_split4(ra[j], h01, h23, l01, l23);
                uint32_t off = (uint32_t)(m * A_STRIDE + kq) * 2;
                *(uint32_t*)(base + off) = h01; *(uint32_t*)(base + off + 4) = h23;
                *(uint32_t*)(base + OFF_ALO + off) = l01; *(uint32_t*)(base + OFF_ALO + off + 4) = l23;
                int kk = idx >> 5, nq = (idx & 31) * 4;
                cvt_split4(rb[j], h01, h23, l01, l23);
                uint32_t boff = (uint32_t)(kk * B_STRIDE + nq) * 2;
                *(uint32_t*)(base + OFF_BHI + boff) = h01; *(uint32_t*)(base + OFF_BHI + boff + 4) = h23;
                *(uint32_t*)(base + OFF_BLO + boff) = l01; *(uint32_t*)(base + OFF_BLO + boff + 4) = l23;
            }
            __syncthreads();
        }
    }

    // epilogue: direct global stores
#pragma unroll
    for (int mt = 0; mt < 4; mt++) {
        const int r = m0 + wm * 64 + mt * 16 + (lane >> 2);
#pragma unroll
        for (int nt = 0; nt < 4; nt++) {
            const int cc = n0 + wn * 32 + nt * 8 + (lane & 3) * 2;
            float* p = Yn + (size_t)r * HW + cc;
            *(float2*)p = make_float2(acc[mt][nt][0], acc[mt][nt][1]);
            *(float2*)(p + 8 * HW) = make_float2(acc[mt][nt][2], acc[mt][nt][3]);
        }
    }
}

// ---------------------------------------------------------------------------
// GroupNorm stats
// ---------------------------------------------------------------------------
__global__ void gn_stats_k(const float* __restrict__ X, float* __restrict__ stats) {
    const int ng = blockIdx.x;
    const float* p = X + (size_t)ng * (CPG * HW);
    const int M = CPG * HW;
    float s = 0.f, s2 = 0.f;
    for (int i = threadIdx.x * 4; i < M; i += blockDim.x * 4) {
        float4 v = *(const float4*)(p + i);
        s  += v.x + v.y + v.z + v.w;
        s2 += v.x * v.x + v.y * v.y + v.z * v.z + v.w * v.w;
    }
    __shared__ float sA[256], sB[256];
    sA[threadIdx.x] = s;
    sB[threadIdx.x] = s2;
    __syncthreads();
    for (int off = 128; off > 0; off >>= 1) {
        if (threadIdx.x < off) {
            sA[threadIdx.x] += sA[threadIdx.x + off];
            sB[threadIdx.x] += sB[threadIdx.x + off];
        }
        __syncthreads();
    }
    if (threadIdx.x == 0) {
        float mean = sA[0] / (float)M;
        float var  = sB[0] / (float)M - mean * mean;
        stats[ng * 2]     = mean;
        stats[ng * 2 + 1] = rsqrtf(var + EPSV);
    }
}

// ---------------------------------------------------------------------------
// GN + SiLU (in-place) + row/col sums
// ---------------------------------------------------------------------------
__global__ void gn_silu_rowcol_k(float* __restrict__ X,
                                 const float* __restrict__ stats,
                                 const float* __restrict__ gamma,
                                 const float* __restrict__ beta,
                                 float* __restrict__ rowsum,
                                 float* __restrict__ colsum) {
    __shared__ float plane[HW];
    const int nc = blockIdx.x;
    const int c = nc & (C_ - 1);
    const int ng = (nc >> 8) * G_ + (c >> 4);
    const float mean = stats[ng * 2];
    const float rstd = stats[ng * 2 + 1];
    const float ga = gamma[c];
    const float be = beta[c];
    float* base = X + (size_t)nc * HW;

    for (int i = threadIdx.x; i < HW; i += 256) {
        float v = base[i];
        v = (v - mean) * rstd * ga + be;
        float sg = 1.f / (1.f + expf(-v));
        v = v * sg;
        plane[i] = v;
        base[i] = v;
    }
    __syncthreads();
    if (threadIdx.x < H_) {
        const int y = threadIdx.x;
        float s = 0.f;
        for (int x = 0; x < W_; x++) s += plane[y * W_ + x];
        rowsum[nc * H_ + y] = s;
    } else if (threadIdx.x < H_ + W_) {
        const int x = threadIdx.x - H_;
        float s = 0.f;
        for (int y = 0; y < H_; y++) s += plane[y * W_ + x];
        colsum[nc * W_ + x] = s;
    }
}

// ---------------------------------------------------------------------------
// gated = 0.25*(rowsum[y] + colsum[x] + 2*h) * sigmoid(gate0 + b_gate[c])
// ---------------------------------------------------------------------------
__global__ void gated_k(const float* __restrict__ h,
                        const float* __restrict__ gate0,
                        const float* __restrict__ rowsum,
                        const float* __restrict__ colsum,
                        const float* __restrict__ b_gate,
                        float* __restrict__ out) {
    const int idx = blockIdx.x * 256 + threadIdx.x;
    const int nc = idx / HW;
    const int hw = idx - nc * HW;
    const int y = hw / W_;
    const int x = hw - y * W_;
    const int c = nc & (C_ - 1);
    float fused = 0.25f * (rowsum[nc * H_ + y] + colsum[nc * W_ + x] + 2.f * h[idx]);
    float gz = gate0[idx] + b_gate[c];
    float gate = 1.f / (1.f + expf(-gz));
    out[idx] = fused * gate;
}

// ---------------------------------------------------------------------------
// depthwise 3x3, padding 1
// ---------------------------------------------------------------------------
__global__ void dw3x3_k(const float* __restrict__ in,
                        const float* __restrict__ wdw,
                        float* __restrict__ out) {
    const int idx = blockIdx.x * 256 + threadIdx.x;
    const int nc = idx / HW;
    const int hw = idx - nc * HW;
    const int y = hw / W_;
    const int x = hw - y * W_;
    const int c = nc & (C_ - 1);
    const float* w = wdw + c * 9;
    const float* p = in + (size_t)nc * HW;
    float s = 0.f;
#pragma unroll
    for (int dy = -1; dy <= 1; dy++) {
        int yy = y + dy;
        if ((unsigned)yy >= H_) continue;
#pragma unroll
        for (int dx = -1; dx <= 1; dx++) {
            int xx = x + dx;
            if ((unsigned)xx >= W_) continue;
            s += w[(dy + 1) * 3 + (dx + 1)] * __ldg(p + yy * W_ + xx);
        }
    }
    out[idx] = s;
}

// ---------------------------------------------------------------------------
// final: out = silu(gn(y))
// ---------------------------------------------------------------------------
__global__ void gn_silu_out_k(const float* __restrict__ X,
                              const float* __restrict__ stats,
                              const float* __restrict__ gamma,
                              const float* __restrict__ beta,
                              float* __restrict__ out) {
    const int idx = blockIdx.x * 256 + threadIdx.x;
    const int nc = idx / HW;
    const int c = nc & (C_ - 1);
    const int ng = (nc >> 8) * G_ + (c >> 4);
    float v = X[idx];
    v = (v - stats[ng * 2]) * stats[ng * 2 + 1] * gamma[c] + beta[c];
    float sg = 1.f / (1.f + expf(-v));
    out[idx] = v * sg;
}

// ---------------------------------------------------------------------------
extern "C" void kernel_launch(void* const* d_in, const int* in_sizes, int n_in,
                              void* d_out, int out_size) {
    const float* x      = (const float*)d_in[0];
    const float* w_pre  = (const float*)d_in[1];
    const float* g1     = (const float*)d_in[2];
    const float* b1     = (const float*)d_in[3];
    const float* w_gate = (const float*)d_in[4];
    const float* b_gate = (const float*)d_in[5];
    const float* w_dw   = (const float*)d_in[6];
    const float* w_pw   = (const float*)d_in[7];
    const float* g2     = (const float*)d_in[8];
    const float* b2     = (const float*)d_in[9];
    float* out = (float*)d_out;

    float *buf1, *buf2, *buf3, *rowsum, *colsum, *stats1, *stats2;
    cudaGetSymbolAddress((void**)&buf1, g_buf1);
    cudaGetSymbolAddress((void**)&buf2, g_buf2);
    cudaGetSymbolAddress((void**)&buf3, g_buf3);
    cudaGetSymbolAddress((void**)&rowsum, g_rowsum);
    cudaGetSymbolAddress((void**)&colsum, g_colsum);
    cudaGetSymbolAddress((void**)&stats1, g_stats1);
    cudaGetSymbolAddress((void**)&stats2, g_stats2);

    cudaFuncSetAttribute(gemm_mma, cudaFuncAttributeMaxDynamicSharedMemorySize,
                         GEMM_SMEM);

    dim3 ggrid(HW / 128, 2, N_);
    const int eblocks = NCHW / 256;

    // 1) h0 = conv1x1(x, w_pre)
    gemm_mma<<<ggrid, 256, GEMM_SMEM>>>(w_pre, x, buf1);
    // 2) GN1 stats
    gn_stats_k<<<N_ * G_, 256>>>(buf1, stats1);
    // 3) h = silu(gn(h0)) in-place + row/col sums
    gn_silu_rowcol_k<<<N_ * C_, 256>>>(buf1, stats1, g1, b1, rowsum, colsum);
    // 4) gate0 = conv1x1(h, w_gate)
    gemm_mma<<<ggrid, 256, GEMM_SMEM>>>(w_gate, buf1, buf2);
    // 5) gated
    gated_k<<<eblocks, 256>>>(buf1, buf2, rowsum, colsum, b_gate, buf3);
    // 6) depthwise 3x3
    dw3x3_k<<<eblocks, 256>>>(buf3, w_dw, buf2);
    // 7) y = conv1x1(dw, w_pw)
    gemm_mma<<<ggrid, 256, GEMM_SMEM>>>(w_pw, buf2, buf1);
    // 8) GN2 stats
    gn_stats_k<<<N_ * G_, 256>>>(buf1, stats2);
    // 9) out = silu(gn(y))
    gn_silu_out_k<<<eblocks, 256>>>(buf1, stats2, g2, b2, out);
}

// round 4
// speedup vs baseline: 1.6534x; 1.0250x over previous
#include <cuda_runtime.h>
#include <cuda_bf16.h>
#include <math.h>
#include <cstdint>

#define C_ 256
#define G_ 16
#define CPG 16
#define N_ 8
#define H_ 80
#define W_ 80
#define HW 6400
#define CHW (C_*HW)
#define NCHW (N_*C_*HW)
#define EPSV 1e-5f
#define NBLK 50   // grid.x of gemm (HW/128)

// Scratch (static device globals; no runtime allocation)
__device__ float g_buf1[NCHW];
__device__ float g_buf2[NCHW];
__device__ float g_buf3[NCHW];
__device__ float g_rowsum[N_*C_*H_];
__device__ float g_colsum[N_*C_*W_];
__device__ float g_stats1[N_*G_*2];
__device__ float g_stats2[N_*G_*2];
__device__ float g_partials[2 * N_ * G_ * NBLK];   // sum | sumsq

__device__ __forceinline__ uint32_t smem_u32(const void* p) {
    uint32_t a;
    asm("{ .reg .u64 t; cvta.to.shared.u64 t, %1; cvt.u32.u64 %0, t; }"
        : "=r"(a) : "l"(p));
    return a;
}

// ===========================================================================
// bf16 split-precision tensor-core GEMM (mma.sync)
// Y[n, o, hw] = sum_c Wm[o,c] * X[n, c, hw]
// CTA tile M=128, N=128, K-chunk 32, double-buffered.
// MODE 0: plain store + per-group GN partial stats
// MODE 1: gated epilogue (uses h, rowsum, colsum, b_gate)
// ===========================================================================
#define A_STRIDE 40
#define B_STRIDE 136
#define OFF_ALO  10240
#define OFF_BHI  20480
#define OFF_BLO  29184
#define STAGE_B  37888
#define GEMM_SMEM (2*STAGE_B)

__device__ __forceinline__ void ldsm_x4(uint32_t* r, uint32_t addr) {
    asm volatile("ldmatrix.sync.aligned.m8n8.x4.shared.b16 {%0,%1,%2,%3}, [%4];"
        : "=r"(r[0]), "=r"(r[1]), "=r"(r[2]), "=r"(r[3]) : "r"(addr));
}
__device__ __forceinline__ void ldsm_x2t(uint32_t* r, uint32_t addr) {
    asm volatile("ldmatrix.sync.aligned.m8n8.x2.trans.shared.b16 {%0,%1}, [%2];"
        : "=r"(r[0]), "=r"(r[1]) : "r"(addr));
}
__device__ __forceinline__ void mma_bf16(float* c, const uint32_t* a, const uint32_t* b) {
    asm volatile(
        "mma.sync.aligned.m16n8k16.row.col.f32.bf16.bf16.f32 "
        "{%0,%1,%2,%3}, {%4,%5,%6,%7}, {%8,%9}, {%0,%1,%2,%3};"
        : "+f"(c[0]), "+f"(c[1]), "+f"(c[2]), "+f"(c[3])
        : "r"(a[0]), "r"(a[1]), "r"(a[2]), "r"(a[3]), "r"(b[0]), "r"(b[1]));
}
__device__ __forceinline__ void cvt_split4(const float4& v, uint32_t& hi01, uint32_t& hi23,
                                           uint32_t& lo01, uint32_t& lo23) {
    __nv_bfloat16 hx = __float2bfloat16(v.x), hy = __float2bfloat16(v.y);
    __nv_bfloat16 hz = __float2bfloat16(v.z), hw = __float2bfloat16(v.w);
    __nv_bfloat162 h01(hx, hy), h23(hz, hw);
    __nv_bfloat162 l01(__float2bfloat16(v.x - __bfloat162float(hx)),
                       __float2bfloat16(v.y - __bfloat162float(hy)));
    __nv_bfloat162 l23(__float2bfloat16(v.z - __bfloat162float(hz)),
                       __float2bfloat16(v.w - __bfloat162float(hw)));
    hi01 = *(uint32_t*)&h01; hi23 = *(uint32_t*)&h23;
    lo01 = *(uint32_t*)&l01; lo23 = *(uint32_t*)&l23;
}

template<int MODE>
__global__ __launch_bounds__(256, 1)
void gemm_mma(const float* __restrict__ Wm, const float* __restrict__ X,
              float* __restrict__ Y,
              float* __restrict__ partials,
              const float* __restrict__ hsrc,
              const float* __restrict__ rowsum,
              const float* __restrict__ colsum,
              const float* __restrict__ b_gate) {
    extern __shared__ char smem[];
    __shared__ float sred[8][4][2];
    const uint32_t sb = smem_u32(smem);
    const int tid = threadIdx.x;
    const int lane = tid & 31;
    const int w = tid >> 5;
    const int wm = w & 1;
    const int wn = w >> 1;
    const int n0 = blockIdx.x * 128;
    const int m0 = blockIdx.y * 128;
    const float* Xn = X + (size_t)blockIdx.z * CHW;
    float* Yn = Y + (size_t)blockIdx.z * CHW;

    float acc[4][4][4];
#pragma unroll
    for (int i = 0; i < 4; i++)
#pragma unroll
        for (int j = 0; j < 4; j++)
#pragma unroll
            for (int q = 0; q < 4; q++) acc[i][j][q] = 0.f;

    float4 ra[4], rb[4];

#pragma unroll
    for (int j = 0; j < 4; j++) {
        int idx = tid + 256 * j;
        int m = idx >> 3, kq = (idx & 7) * 4;
        ra[j] = *(const float4*)(Wm + (size_t)(m0 + m) * 256 + kq);
        int kk = idx >> 5, nq = (idx & 31) * 4;
        rb[j] = *(const float4*)(Xn + (size_t)kk * HW + n0 + nq);
    }
    {
        char* base = smem;
#pragma unroll
        for (int j = 0; j < 4; j++) {
            int idx = tid + 256 * j;
            int m = idx >> 3, kq = (idx & 7) * 4;
            uint32_t h01, h23, l01, l23;
            cvt_split4(ra[j], h01, h23, l01, l23);
            uint32_t off = (uint32_t)(m * A_STRIDE + kq) * 2;
            *(uint32_t*)(base + off) = h01; *(uint32_t*)(base + off + 4) = h23;
            *(uint32_t*)(base + OFF_ALO + off) = l01; *(uint32_t*)(base + OFF_ALO + off + 4) = l23;
            int kk = idx >> 5, nq = (idx & 31) * 4;
            cvt_split4(rb[j], h01, h23, l01, l23);
            uint32_t boff = (uint32_t)(kk * B_STRIDE + nq) * 2;
            *(uint32_t*)(base + OFF_BHI + boff) = h01; *(uint32_t*)(base + OFF_BHI + boff + 4) = h23;
            *(uint32_t*)(base + OFF_BLO + boff) = l01; *(uint32_t*)(base + OFF_BLO + boff + 4) = l23;
        }
    }
    __syncthreads();

    const uint32_t a_lane_off = (uint32_t)((lane & 15) * A_STRIDE + ((lane >> 4) << 3)) * 2;
    const uint32_t b_lane_off = (uint32_t)((lane & 15) * B_STRIDE) * 2;

    for (int ch = 0; ch < 8; ch++) {
        const int st = ch & 1;
        if (ch < 7) {
            const int k0 = (ch + 1) * 32;
#pragma unroll
            for (int j = 0; j < 4; j++) {
                int idx = tid + 256 * j;
                int m = idx >> 3, kq = (idx & 7) * 4;
                ra[j] = *(const float4*)(Wm + (size_t)(m0 + m) * 256 + k0 + kq);
                int kk = idx >> 5, nq = (idx & 31) * 4;
                rb[j] = *(const float4*)(Xn + (size_t)(k0 + kk) * HW + n0 + nq);
            }
        }
        {
            const uint32_t SB = sb + st * STAGE_B;
            const uint32_t a_base = SB + (uint32_t)(wm * 64) * (A_STRIDE * 2) + a_lane_off;
#pragma unroll
            for (int ks = 0; ks < 2; ks++) {
                const uint32_t kb = (uint32_t)(ks * 16);
                uint32_t ah[4][4], al[4][4], bh[4][2], bl[4][2];
#pragma unroll
                for (int mt = 0; mt < 4; mt++) {
                    uint32_t ad = a_base + (uint32_t)(mt * 16) * (A_STRIDE * 2) + kb * 2;
                    ldsm_x4(ah[mt], ad);
                    ldsm_x4(al[mt], ad + OFF_ALO);
                }
#pragma unroll
                for (int nt = 0; nt < 4; nt++) {
                    uint32_t bd = SB + OFF_BHI + b_lane_off + kb * (B_STRIDE * 2)
                                  + (uint32_t)(wn * 32 + nt * 8) * 2;
                    ldsm_x2t(bh[nt], bd);
                    ldsm_x2t(bl[nt], bd + (OFF_BLO - OFF_BHI));
                }
#pragma unroll
                for (int mt = 0; mt < 4; mt++)
#pragma unroll
                    for (int nt = 0; nt < 4; nt++) {
                        mma_bf16(acc[mt][nt], ah[mt], bh[nt]);
                        mma_bf16(acc[mt][nt], ah[mt], bl[nt]);
                        mma_bf16(acc[mt][nt], al[mt], bh[nt]);
                    }
            }
        }
        if (ch < 7) {
            char* base = smem + ((ch + 1) & 1) * STAGE_B;
#pragma unroll
            for (int j = 0; j < 4; j++) {
                int idx = tid + 256 * j;
                int m = idx >> 3, kq = (idx & 7) * 4;
                uint32_t h01, h23, l01, l23;
                cvt_split4(ra[j], h01, h23, l01, l23);
                uint32_t off = (uint32_t)(m * A_STRIDE + kq) * 2;
                *(uint32_t*)(base + off) = h01; *(uint32_t*)(base + off + 4) = h23;
                *(uint32_t*)(base + OFF_ALO + off) = l01; *(uint32_t*)(base + OFF_ALO + off + 4) = l23;
                int kk = idx >> 5, nq = (idx & 31) * 4;
                cvt_split4(rb[j], h01, h23, l01, l23);
                uint32_t boff = (uint32_t)(kk * B_STRIDE + nq) * 2;
                *(uint32_t*)(base + OFF_BHI + boff) = h01; *(uint32_t*)(base + OFF_BHI + boff + 4) = h23;
                *(uint32_t*)(base + OFF_BLO + boff) = l01; *(uint32_t*)(base + OFF_BLO + boff + 4) = l23;
            }
            __syncthreads();
        }
    }

    if (MODE == 0) {
        // store + per-group partial stats
        float s[4], s2[4];
#pragma unroll
        for (int mt = 0; mt < 4; mt++) { s[mt] = 0.f; s2[mt] = 0.f; }
#pragma unroll
        for (int mt = 0; mt < 4; mt++) {
            const int r = m0 + wm * 64 + mt * 16 + (lane >> 2);
#pragma unroll
            for (int nt = 0; nt < 4; nt++) {
                const int cc = n0 + wn * 32 + nt * 8 + (lane & 3) * 2;
                float* p = Yn + (size_t)r * HW + cc;
                *(float2*)p = make_float2(acc[mt][nt][0], acc[mt][nt][1]);
                *(float2*)(p + 8 * HW) = make_float2(acc[mt][nt][2], acc[mt][nt][3]);
#pragma unroll
                for (int q = 0; q < 4; q++) {
                    float v = acc[mt][nt][q];
                    s[mt] += v; s2[mt] += v * v;
                }
            }
        }
#pragma unroll
        for (int mt = 0; mt < 4; mt++) {
#pragma unroll
            for (int off = 16; off > 0; off >>= 1) {
                s[mt]  += __shfl_down_sync(0xFFFFFFFFu, s[mt], off);
                s2[mt] += __shfl_down_sync(0xFFFFFFFFu, s2[mt], off);
            }
        }
        __syncthreads();   // stage smem no longer needed
        if (lane == 0) {
#pragma unroll
            for (int mt = 0; mt < 4; mt++) {
                sred[w][mt][0] = s[mt];
                sred[w][mt][1] = s2[mt];
            }
        }
        __syncthreads();
        if (tid < 8) {
            const int twm = tid >> 2, tmt = tid & 3;
            float S = 0.f, S2 = 0.f;
#pragma unroll
            for (int j = 0; j < 4; j++) {
                S  += sred[twm + 2 * j][tmt][0];
                S2 += sred[twm + 2 * j][tmt][1];
            }
            const int g = blockIdx.y * 8 + twm * 4 + tmt;
            const int ng = blockIdx.z * G_ + g;
            partials[ng * NBLK + blockIdx.x] = S;
            partials[N_ * G_ * NBLK + ng * NBLK + blockIdx.x] = S2;
        }
    } else {
        // gated epilogue
        const float* hn = hsrc + (size_t)blockIdx.z * CHW;
#pragma unroll
        for (int mt = 0; mt < 4; mt++) {
            const int r0 = m0 + wm * 64 + mt * 16 + (lane >> 2);
#pragma unroll
            for (int nt = 0; nt < 4; nt++) {
                const int cc = n0 + wn * 32 + nt * 8 + (lane & 3) * 2;
#pragma unroll
                for (int half = 0; half < 2; half++) {
                    const int r = r0 + half * 8;
                    const int nc = blockIdx.z * C_ + r;
                    const float bg = b_gate[r];
                    const float hv0 = hn[(size_t)r * HW + cc];
                    const float hv1 = hn[(size_t)r * HW + cc + 1];
                    float o[2];
#pragma unroll
                    for (int e = 0; e < 2; e++) {
                        const int hw = cc + e;
                        const int y = hw / W_;
                        const int x = hw - y * W_;
                        const float hv = e ? hv1 : hv0;
                        float fused = 0.25f * (rowsum[nc * H_ + y] + colsum[nc * W_ + x] + 2.f * hv);
                        float gz = acc[mt][nt][half * 2 + e] + bg;
                        o[e] = fused / (1.f + expf(-gz));
                    }
                    *(float2*)(Yn + (size_t)r * HW + cc) = make_float2(o[0], o[1]);
                }
            }
        }
    }
}

// ---------------------------------------------------------------------------
// finalize GN stats from partials
// ---------------------------------------------------------------------------
__global__ void finalize_stats_k(const float* __restrict__ partials,
                                 float* __restrict__ stats) {
    const int ng = threadIdx.x;   // 0..127
    float s = 0.f, s2 = 0.f;
    for (int b = 0; b < NBLK; b++) {
        s  += partials[ng * NBLK + b];
        s2 += partials[N_ * G_ * NBLK + ng * NBLK + b];
    }
    const float M = (float)(CPG * HW);
    float mean = s / M;
    float var = s2 / M - mean * mean;
    stats[ng * 2] = mean;
    stats[ng * 2 + 1] = rsqrtf(var + EPSV);
}

// ---------------------------------------------------------------------------
// GN + SiLU (in-place) + row/col sums
// ---------------------------------------------------------------------------
__global__ void gn_silu_rowcol_k(float* __restrict__ X,
                                 const float* __restrict__ stats,
                                 const float* __restrict__ gamma,
                                 const float* __restrict__ beta,
                                 float* __restrict__ rowsum,
                                 float* __restrict__ colsum) {
    __shared__ float plane[HW];
    const int nc = blockIdx.x;
    const int c = nc & (C_ - 1);
    const int ng = (nc >> 8) * G_ + (c >> 4);
    const float mean = stats[ng * 2];
    const float rstd = stats[ng * 2 + 1];
    const float ga = gamma[c];
    const float be = beta[c];
    float* base = X + (size_t)nc * HW;

    for (int i = threadIdx.x; i < HW; i += 256) {
        float v = base[i];
        v = (v - mean) * rstd * ga + be;
        float sg = 1.f / (1.f + expf(-v));
        v = v * sg;
        plane[i] = v;
        base[i] = v;
    }
    __syncthreads();
    if (threadIdx.x < H_) {
        const int y = threadIdx.x;
        float s = 0.f;
        for (int x = 0; x < W_; x++) s += plane[y * W_ + x];
        rowsum[nc * H_ + y] = s;
    } else if (threadIdx.x < H_ + W_) {
        const int x = threadIdx.x - H_;
        float s = 0.f;
        for (int y = 0; y < H_; y++) s += plane[y * W_ + x];
        colsum[nc * W_ + x] = s;
    }
}

// ---------------------------------------------------------------------------
// depthwise 3x3, padding 1
// ---------------------------------------------------------------------------
__global__ void dw3x3_k(const float* __restrict__ in,
                        const float* __restrict__ wdw,
                        float* __restrict__ out) {
    const int idx = blockIdx.x * 256 + threadIdx.x;
    const int nc = idx / HW;
    const int hw = idx - nc * HW;
    const int y = hw / W_;
    const int x = hw - y * W_;
    const int c = nc & (C_ - 1);
    const float* w = wdw + c * 9;
    const float* p = in + (size_t)nc * HW;
    float s = 0.f;
#pragma unroll
    for (int dy = -1; dy <= 1; dy++) {
        int yy = y + dy;
        if ((unsigned)yy >= H_) continue;
#pragma unroll
        for (int dx = -1; dx <= 1; dx++) {
            int xx = x + dx;
            if ((unsigned)xx >= W_) continue;
            s += w[(dy + 1) * 3 + (dx + 1)] * __ldg(p + yy * W_ + xx);
        }
    }
    out[idx] = s;
}

// ---------------------------------------------------------------------------
// final: out = silu(gn(y))
// ---------------------------------------------------------------------------
__global__ void gn_silu_out_k(const float* __restrict__ X,
                              const float* __restrict__ stats,
                              const float* __restrict__ gamma,
                              const float* __restrict__ beta,
                              float* __restrict__ out) {
    const int idx = blockIdx.x * 256 + threadIdx.x;
    const int nc = idx / HW;
    const int c = nc & (C_ - 1);
    const int ng = (nc >> 8) * G_ + (c >> 4);
    float v = X[idx];
    v = (v - stats[ng * 2]) * stats[ng * 2 + 1] * gamma[c] + beta[c];
    float sg = 1.f / (1.f + expf(-v));
    out[idx] = v * sg;
}

// ---------------------------------------------------------------------------
extern "C" void kernel_launch(void* const* d_in, const int* in_sizes, int n_in,
                              void* d_out, int out_size) {
    const float* x      = (const float*)d_in[0];
    const float* w_pre  = (const float*)d_in[1];
    const float* g1     = (const float*)d_in[2];
    const float* b1     = (const float*)d_in[3];
    const float* w_gate = (const float*)d_in[4];
    const float* b_gate = (const float*)d_in[5];
    const float* w_dw   = (const float*)d_in[6];
    const float* w_pw   = (const float*)d_in[7];
    const float* g2     = (const float*)d_in[8];
    const float* b2     = (const float*)d_in[9];
    float* out = (float*)d_out;

    float *buf1, *buf2, *buf3, *rowsum, *colsum, *stats1, *stats2, *partials;
    cudaGetSymbolAddress((void**)&buf1, g_buf1);
    cudaGetSymbolAddress((void**)&buf2, g_buf2);
    cudaGetSymbolAddress((void**)&buf3, g_buf3);
    cudaGetSymbolAddress((void**)&rowsum, g_rowsum);
    cudaGetSymbolAddress((void**)&colsum, g_colsum);
    cudaGetSymbolAddress((void**)&stats1, g_stats1);
    cudaGetSymbolAddress((void**)&stats2, g_stats2);
    cudaGetSymbolAddress((void**)&partials, g_partials);

    cudaFuncSetAttribute(gemm_mma<0>, cudaFuncAttributeMaxDynamicSharedMemorySize, GEMM_SMEM);
    cudaFuncSetAttribute(gemm_mma<1>, cudaFuncAttributeMaxDynamicSharedMemorySize, GEMM_SMEM);

    dim3 ggrid(NBLK, 2, N_);
    const int eblocks = NCHW / 256;

    // 1) h0 = conv1x1(x, w_pre) + GN1 partial stats
    gemm_mma<0><<<ggrid, 256, GEMM_SMEM>>>(w_pre, x, buf1, partials, nullptr, nullptr, nullptr, nullptr);
    finalize_stats_k<<<1, 128>>>(partials, stats1);
    // 2) h = silu(gn(h0)) in-place + row/col sums
    gn_silu_rowcol_k<<<N_ * C_, 256>>>(buf1, stats1, g1, b1, rowsum, colsum);
    // 3) gated = fused * sigmoid(conv1x1(h,w_gate)+b)   (fused epilogue)
    gemm_mma<1><<<ggrid, 256, GEMM_SMEM>>>(w_gate, buf1, buf3, nullptr, buf1, rowsum, colsum, b_gate);
    // 4) depthwise 3x3
    dw3x3_k<<<eblocks, 256>>>(buf3, w_dw, buf2);
    // 5) y = conv1x1(dw, w_pw) + GN2 partial stats
    gemm_mma<0><<<ggrid, 256, GEMM_SMEM>>>(w_pw, buf2, buf1, partials, nullptr, nullptr, nullptr, nullptr);
    finalize_stats_k<<<1, 128>>>(partials, stats2);
    // 6) out = silu(gn(y))
    gn_silu_out_k<<<eblocks, 256>>>(buf1, stats2, g2, b2, out);
}

// round 5
// speedup vs baseline: 1.7467x; 1.0564x over previous
#include <cuda_runtime.h>
#include <cuda_bf16.h>
#include <math.h>
#include <cstdint>

#define C_ 256
#define G_ 16
#define CPG 16
#define N_ 8
#define H_ 80
#define W_ 80
#define HW 6400
#define CHW (C_*HW)
#define NCHW (N_*C_*HW)
#define EPSV 1e-5f
#define NBLK 50   // grid.x of gemm (HW/128)

// Scratch (static device globals; no runtime allocation)
__device__ float g_buf1[NCHW];
__device__ float g_buf2[NCHW];
__device__ float g_buf3[NCHW];
__device__ float g_stats1[N_*G_*2];
__device__ float g_stats2[N_*G_*2];
__device__ float g_partials[2 * N_ * G_ * NBLK];   // sum | sumsq

__device__ __forceinline__ uint32_t smem_u32(const void* p) {
    uint32_t a;
    asm("{ .reg .u64 t; cvta.to.shared.u64 t, %1; cvt.u32.u64 %0, t; }"
        : "=r"(a) : "l"(p));
    return a;
}

// ===========================================================================
// bf16 split-precision tensor-core GEMM (mma.sync)
// Y[n, o, hw] = sum_c Wm[o,c] * X[n, c, hw]
// CTA tile M=128, N=128, K-chunk 32, double-buffered.
// MODE 0: plain store + per-group GN partial stats
// MODE 1: gated epilogue: Y = fused * sigmoid(acc + b_gate)   (fused coalesced)
// ===========================================================================
#define A_STRIDE 40
#define B_STRIDE 136
#define OFF_ALO  10240
#define OFF_BHI  20480
#define OFF_BLO  29184
#define STAGE_B  37888
#define GEMM_SMEM (2*STAGE_B)

__device__ __forceinline__ void ldsm_x4(uint32_t* r, uint32_t addr) {
    asm volatile("ldmatrix.sync.aligned.m8n8.x4.shared.b16 {%0,%1,%2,%3}, [%4];"
        : "=r"(r[0]), "=r"(r[1]), "=r"(r[2]), "=r"(r[3]) : "r"(addr));
}
__device__ __forceinline__ void ldsm_x2t(uint32_t* r, uint32_t addr) {
    asm volatile("ldmatrix.sync.aligned.m8n8.x2.trans.shared.b16 {%0,%1}, [%2];"
        : "=r"(r[0]), "=r"(r[1]) : "r"(addr));
}
__device__ __forceinline__ void mma_bf16(float* c, const uint32_t* a, const uint32_t* b) {
    asm volatile(
        "mma.sync.aligned.m16n8k16.row.col.f32.bf16.bf16.f32 "
        "{%0,%1,%2,%3}, {%4,%5,%6,%7}, {%8,%9}, {%0,%1,%2,%3};"
        : "+f"(c[0]), "+f"(c[1]), "+f"(c[2]), "+f"(c[3])
        : "r"(a[0]), "r"(a[1]), "r"(a[2]), "r"(a[3]), "r"(b[0]), "r"(b[1]));
}
__device__ __forceinline__ void cvt_split4(const float4& v, uint32_t& hi01, uint32_t& hi23,
                                           uint32_t& lo01, uint32_t& lo23) {
    __nv_bfloat16 hx = __float2bfloat16(v.x), hy = __float2bfloat16(v.y);
    __nv_bfloat16 hz = __float2bfloat16(v.z), hw = __float2bfloat16(v.w);
    __nv_bfloat162 h01(hx, hy), h23(hz, hw);
    __nv_bfloat162 l01(__float2bfloat16(v.x - __bfloat162float(hx)),
                       __float2bfloat16(v.y - __bfloat162float(hy)));
    __nv_bfloat162 l23(__float2bfloat16(v.z - __bfloat162float(hz)),
                       __float2bfloat16(v.w - __bfloat162float(hw)));
    hi01 = *(uint32_t*)&h01; hi23 = *(uint32_t*)&h23;
    lo01 = *(uint32_t*)&l01; lo23 = *(uint32_t*)&l23;
}

template<int MODE>
__global__ __launch_bounds__(256, 1)
void gemm_mma(const float* __restrict__ Wm, const float* __restrict__ X,
              float* __restrict__ Y,
              float* __restrict__ partials,
              const float* __restrict__ fusedsrc,
              const float* __restrict__ b_gate) {
    extern __shared__ char smem[];
    __shared__ float sred[8][4][2];
    const uint32_t sb = smem_u32(smem);
    const int tid = threadIdx.x;
    const int lane = tid & 31;
    const int w = tid >> 5;
    const int wm = w & 1;
    const int wn = w >> 1;
    const int n0 = blockIdx.x * 128;
    const int m0 = blockIdx.y * 128;
    const float* Xn = X + (size_t)blockIdx.z * CHW;
    float* Yn = Y + (size_t)blockIdx.z * CHW;

    float acc[4][4][4];
#pragma unroll
    for (int i = 0; i < 4; i++)
#pragma unroll
        for (int j = 0; j < 4; j++)
#pragma unroll
            for (int q = 0; q < 4; q++) acc[i][j][q] = 0.f;

    float4 ra[4], rb[4];

#pragma unroll
    for (int j = 0; j < 4; j++) {
        int idx = tid + 256 * j;
        int m = idx >> 3, kq = (idx & 7) * 4;
        ra[j] = *(const float4*)(Wm + (size_t)(m0 + m) * 256 + kq);
        int kk = idx >> 5, nq = (idx & 31) * 4;
        rb[j] = *(const float4*)(Xn + (size_t)kk * HW + n0 + nq);
    }
    {
        char* base = smem;
#pragma unroll
        for (int j = 0; j < 4; j++) {
            int idx = tid + 256 * j;
            int m = idx >> 3, kq = (idx & 7) * 4;
            uint32_t h01, h23, l01, l23;
            cvt_split4(ra[j], h01, h23, l01, l23);
            uint32_t off = (uint32_t)(m * A_STRIDE + kq) * 2;
            *(uint32_t*)(base + off) = h01; *(uint32_t*)(base + off + 4) = h23;
            *(uint32_t*)(base + OFF_ALO + off) = l01; *(uint32_t*)(base + OFF_ALO + off + 4) = l23;
            int kk = idx >> 5, nq = (idx & 31) * 4;
            cvt_split4(rb[j], h01, h23, l01, l23);
            uint32_t boff = (uint32_t)(kk * B_STRIDE + nq) * 2;
            *(uint32_t*)(base + OFF_BHI + boff) = h01; *(uint32_t*)(base + OFF_BHI + boff + 4) = h23;
            *(uint32_t*)(base + OFF_BLO + boff) = l01; *(uint32_t*)(base + OFF_BLO + boff + 4) = l23;
        }
    }
    __syncthreads();

    const uint32_t a_lane_off = (uint32_t)((lane & 15) * A_STRIDE + ((lane >> 4) << 3)) * 2;
    const uint32_t b_lane_off = (uint32_t)((lane & 15) * B_STRIDE) * 2;

    for (int ch = 0; ch < 8; ch++) {
        const int st = ch & 1;
        if (ch < 7) {
            const int k0 = (ch + 1) * 32;
#pragma unroll
            for (int j = 0; j < 4; j++) {
                int idx = tid + 256 * j;
                int m = idx >> 3, kq = (idx & 7) * 4;
                ra[j] = *(const float4*)(Wm + (size_t)(m0 + m) * 256 + k0 + kq);
                int kk = idx >> 5, nq = (idx & 31) * 4;
                rb[j] = *(const float4*)(Xn + (size_t)(k0 + kk) * HW + n0 + nq);
            }
        }
        {
            const uint32_t SB = sb + st * STAGE_B;
            const uint32_t a_base = SB + (uint32_t)(wm * 64) * (A_STRIDE * 2) + a_lane_off;
#pragma unroll
            for (int ks = 0; ks < 2; ks++) {
                const uint32_t kb = (uint32_t)(ks * 16);
                uint32_t ah[4][4], al[4][4], bh[4][2], bl[4][2];
#pragma unroll
                for (int mt = 0; mt < 4; mt++) {
                    uint32_t ad = a_base + (uint32_t)(mt * 16) * (A_STRIDE * 2) + kb * 2;
                    ldsm_x4(ah[mt], ad);
                    ldsm_x4(al[mt], ad + OFF_ALO);
                }
#pragma unroll
                for (int nt = 0; nt < 4; nt++) {
                    uint32_t bd = SB + OFF_BHI + b_lane_off + kb * (B_STRIDE * 2)
                                  + (uint32_t)(wn * 32 + nt * 8) * 2;
                    ldsm_x2t(bh[nt], bd);
                    ldsm_x2t(bl[nt], bd + (OFF_BLO - OFF_BHI));
                }
#pragma unroll
                for (int mt = 0; mt < 4; mt++)
#pragma unroll
                    for (int nt = 0; nt < 4; nt++) {
                        mma_bf16(acc[mt][nt], ah[mt], bh[nt]);
                        mma_bf16(acc[mt][nt], ah[mt], bl[nt]);
                        mma_bf16(acc[mt][nt], al[mt], bh[nt]);
                    }
            }
        }
        if (ch < 7) {
            char* base = smem + ((ch + 1) & 1) * STAGE_B;
#pragma unroll
            for (int j = 0; j < 4; j++) {
                int idx = tid + 256 * j;
                int m = idx >> 3, kq = (idx & 7) * 4;
                uint32_t h01, h23, l01, l23;
                cvt_split4(ra[j], h01, h23, l01, l23);
                uint32_t off = (uint32_t)(m * A_STRIDE + kq) * 2;
                *(uint32_t*)(base + off) = h01; *(uint32_t*)(base + off + 4) = h23;
                *(uint32_t*)(base + OFF_ALO + off) = l01; *(uint32_t*)(base + OFF_ALO + off + 4) = l23;
                int kk = idx >> 5, nq = (idx & 31) * 4;
                cvt_split4(rb[j], h01, h23, l01, l23);
                uint32_t boff = (uint32_t)(kk * B_STRIDE + nq) * 2;
                *(uint32_t*)(base + OFF_BHI + boff) = h01; *(uint32_t*)(base + OFF_BHI + boff + 4) = h23;
                *(uint32_t*)(base + OFF_BLO + boff) = l01; *(uint32_t*)(base + OFF_BLO + boff + 4) = l23;
            }
            __syncthreads();
        }
    }

    if (MODE == 0) {
        float s[4], s2[4];
#pragma unroll
        for (int mt = 0; mt < 4; mt++) { s[mt] = 0.f; s2[mt] = 0.f; }
#pragma unroll
        for (int mt = 0; mt < 4; mt++) {
            const int r = m0 + wm * 64 + mt * 16 + (lane >> 2);
#pragma unroll
            for (int nt = 0; nt < 4; nt++) {
                const int cc = n0 + wn * 32 + nt * 8 + (lane & 3) * 2;
                float* p = Yn + (size_t)r * HW + cc;
                *(float2*)p = make_float2(acc[mt][nt][0], acc[mt][nt][1]);
                *(float2*)(p + 8 * HW) = make_float2(acc[mt][nt][2], acc[mt][nt][3]);
#pragma unroll
                for (int q = 0; q < 4; q++) {
                    float v = acc[mt][nt][q];
                    s[mt] += v; s2[mt] += v * v;
                }
            }
        }
#pragma unroll
        for (int mt = 0; mt < 4; mt++) {
#pragma unroll
            for (int off = 16; off > 0; off >>= 1) {
                s[mt]  += __shfl_down_sync(0xFFFFFFFFu, s[mt], off);
                s2[mt] += __shfl_down_sync(0xFFFFFFFFu, s2[mt], off);
            }
        }
        __syncthreads();
        if (lane == 0) {
#pragma unroll
            for (int mt = 0; mt < 4; mt++) {
                sred[w][mt][0] = s[mt];
                sred[w][mt][1] = s2[mt];
            }
        }
        __syncthreads();
        if (tid < 8) {
            const int twm = tid >> 2, tmt = tid & 3;
            float S = 0.f, S2 = 0.f;
#pragma unroll
            for (int j = 0; j < 4; j++) {
                S  += sred[twm + 2 * j][tmt][0];
                S2 += sred[twm + 2 * j][tmt][1];
            }
            const int g = blockIdx.y * 8 + twm * 4 + tmt;
            const int ng = blockIdx.z * G_ + g;
            partials[ng * NBLK + blockIdx.x] = S;
            partials[N_ * G_ * NBLK + ng * NBLK + blockIdx.x] = S2;
        }
    } else {
        // gated epilogue: Y = fused * sigmoid(acc + b_gate)   (all coalesced)
        const float* fn = fusedsrc + (size_t)blockIdx.z * CHW;
#pragma unroll
        for (int mt = 0; mt < 4; mt++) {
            const int r0 = m0 + wm * 64 + mt * 16 + (lane >> 2);
#pragma unroll
            for (int nt = 0; nt < 4; nt++) {
                const int cc = n0 + wn * 32 + nt * 8 + (lane & 3) * 2;
#pragma unroll
                for (int half = 0; half < 2; half++) {
                    const int r = r0 + half * 8;
                    const float bg = b_gate[r];
                    float2 fv = *(const float2*)(fn + (size_t)r * HW + cc);
                    float g0 = 1.f / (1.f + expf(-(acc[mt][nt][half * 2 + 0] + bg)));
                    float g1 = 1.f / (1.f + expf(-(acc[mt][nt][half * 2 + 1] + bg)));
                    *(float2*)(Yn + (size_t)r * HW + cc) =
                        make_float2(fv.x * g0, fv.y * g1);
                }
            }
        }
    }
}

// ---------------------------------------------------------------------------
// finalize GN stats from partials
// ---------------------------------------------------------------------------
__global__ void finalize_stats_k(const float* __restrict__ partials,
                                 float* __restrict__ stats) {
    const int ng = threadIdx.x;   // 0..127
    float s = 0.f, s2 = 0.f;
    for (int b = 0; b < NBLK; b++) {
        s  += partials[ng * NBLK + b];
        s2 += partials[N_ * G_ * NBLK + ng * NBLK + b];
    }
    const float M = (float)(CPG * HW);
    float mean = s / M;
    float var = s2 / M - mean * mean;
    stats[ng * 2] = mean;
    stats[ng * 2 + 1] = rsqrtf(var + EPSV);
}

// ---------------------------------------------------------------------------
// GN + SiLU (in-place on X) + fused = 0.25*(rowsum[y]+colsum[x]+2h) -> F
// One block per (n,c) plane. rowsum/colsum live only in smem.
// ---------------------------------------------------------------------------
__global__ void gn_silu_rowcol_k(float* __restrict__ X,
                                 const float* __restrict__ stats,
                                 const float* __restrict__ gamma,
                                 const float* __restrict__ beta,
                                 float* __restrict__ F) {
    __shared__ float plane[HW];
    __shared__ float rs[H_], cs[W_];
    const int nc = blockIdx.x;
    const int c = nc & (C_ - 1);
    const int ng = (nc >> 8) * G_ + (c >> 4);
    const float mean = stats[ng * 2];
    const float rstd = stats[ng * 2 + 1];
    const float ga = gamma[c];
    const float be = beta[c];
    float* base = X + (size_t)nc * HW;
    float* fb = F + (size_t)nc * HW;

    for (int i = threadIdx.x; i < HW; i += 256) {
        float v = base[i];
        v = (v - mean) * rstd * ga + be;
        float sg = 1.f / (1.f + expf(-v));
        v = v * sg;
        plane[i] = v;
        base[i] = v;
    }
    __syncthreads();
    if (threadIdx.x < H_) {
        const int y = threadIdx.x;
        float s = 0.f;
#pragma unroll 8
        for (int x = 0; x < W_; x++) s += plane[y * W_ + x];
        rs[y] = s;
    } else if (threadIdx.x < H_ + W_) {
        const int x = threadIdx.x - H_;
        float s = 0.f;
#pragma unroll 8
        for (int y = 0; y < H_; y++) s += plane[y * W_ + x];
        cs[x] = s;
    }
    __syncthreads();
    for (int i = threadIdx.x; i < HW; i += 256) {
        const int y = i / W_;
        const int x = i - y * W_;
        fb[i] = 0.25f * (rs[y] + cs[x] + 2.f * plane[i]);
    }
}

// ---------------------------------------------------------------------------
// depthwise 3x3, padding 1 — plane-tiled in smem
// ---------------------------------------------------------------------------
__global__ void dw3x3_k(const float* __restrict__ in,
                        const float* __restrict__ wdw,
                        float* __restrict__ out) {
    __shared__ float pl[HW];
    const int nc = blockIdx.x;
    const int c = nc & (C_ - 1);
    float wr[9];
#pragma unroll
    for (int q = 0; q < 9; q++) wr[q] = __ldg(wdw + c * 9 + q);
    const float* p = in + (size_t)nc * HW;
    float* o = out + (size_t)nc * HW;
    for (int i = threadIdx.x; i < HW; i += 256) pl[i] = p[i];
    __syncthreads();
    for (int i = threadIdx.x; i < HW; i += 256) {
        const int y = i / W_;
        const int x = i - y * W_;
        float s = 0.f;
#pragma unroll
        for (int dy = -1; dy <= 1; dy++) {
            const int yy = y + dy;
            if ((unsigned)yy >= H_) continue;
#pragma unroll
            for (int dx = -1; dx <= 1; dx++) {
                const int xx = x + dx;
                if ((unsigned)xx >= W_) continue;
                s += wr[(dy + 1) * 3 + (dx + 1)] * pl[yy * W_ + xx];
            }
        }
        o[i] = s;
    }
}

// ---------------------------------------------------------------------------
// final: out = silu(gn(y))
// ---------------------------------------------------------------------------
__global__ void gn_silu_out_k(const float* __restrict__ X,
                              const float* __restrict__ stats,
                              const float* __restrict__ gamma,
                              const float* __restrict__ beta,
                              float* __restrict__ out) {
    const int idx = blockIdx.x * 256 + threadIdx.x;
    const int nc = idx / HW;
    const int c = nc & (C_ - 1);
    const int ng = (nc >> 8) * G_ + (c >> 4);
    float v = X[idx];
    v = (v - stats[ng * 2]) * stats[ng * 2 + 1] * gamma[c] + beta[c];
    float sg = 1.f / (1.f + expf(-v));
    out[idx] = v * sg;
}

// ---------------------------------------------------------------------------
extern "C" void kernel_launch(void* const* d_in, const int* in_sizes, int n_in,
                              void* d_out, int out_size) {
    const float* x      = (const float*)d_in[0];
    const float* w_pre  = (const float*)d_in[1];
    const float* g1     = (const float*)d_in[2];
    const float* b1     = (const float*)d_in[3];
    const float* w_gate = (const float*)d_in[4];
    const float* b_gate = (const float*)d_in[5];
    const float* w_dw   = (const float*)d_in[6];
    const float* w_pw   = (const float*)d_in[7];
    const float* g2     = (const float*)d_in[8];
    const float* b2     = (const float*)d_in[9];
    float* out = (float*)d_out;

    float *buf1, *buf2, *buf3, *stats1, *stats2, *partials;
    cudaGetSymbolAddress((void**)&buf1, g_buf1);
    cudaGetSymbolAddress((void**)&buf2, g_buf2);
    cudaGetSymbolAddress((void**)&buf3, g_buf3);
    cudaGetSymbolAddress((void**)&stats1, g_stats1);
    cudaGetSymbolAddress((void**)&stats2, g_stats2);
    cudaGetSymbolAddress((void**)&partials, g_partials);

    cudaFuncSetAttribute(gemm_mma<0>, cudaFuncAttributeMaxDynamicSharedMemorySize, GEMM_SMEM);
    cudaFuncSetAttribute(gemm_mma<1>, cudaFuncAttributeMaxDynamicSharedMemorySize, GEMM_SMEM);

    dim3 ggrid(NBLK, 2, N_);
    const int eblocks = NCHW / 256;

    // 1) h0 = conv1x1(x, w_pre) + GN1 partial stats
    gemm_mma<0><<<ggrid, 256, GEMM_SMEM>>>(w_pre, x, buf1, partials, nullptr, nullptr);
    finalize_stats_k<<<1, 128>>>(partials, stats1);
    // 2) h = silu(gn(h0)) in-place + fused -> buf2
    gn_silu_rowcol_k<<<N_ * C_, 256>>>(buf1, stats1, g1, b1, buf2);
    // 3) gated = fused * sigmoid(conv1x1(h,w_gate)+b) -> buf3
    gemm_mma<1><<<ggrid, 256, GEMM_SMEM>>>(w_gate, buf1, buf3, nullptr, buf2, b_gate);
    // 4) depthwise 3x3: buf3 -> buf2
    dw3x3_k<<<N_ * C_, 256>>>(buf3, w_dw, buf2);
    // 5) y = conv1x1(dw, w_pw) + GN2 partial stats
    gemm_mma<0><<<ggrid, 256, GEMM_SMEM>>>(w_pw, buf2, buf1, partials, nullptr, nullptr);
    finalize_stats_k<<<1, 128>>>(partials, stats2);
    // 6) out = silu(gn(y))
    gn_silu_out_k<<<eblocks, 256>>>(buf1, stats2, g2, b2, out);
}

// round 6
// speedup vs baseline: 1.8876x; 1.0807x over previous
#include <cuda_runtime.h>
#include <cuda_bf16.h>
#include <math.h>
#include <cstdint>

#define C_ 256
#define G_ 16
#define CPG 16
#define N_ 8
#define H_ 80
#define W_ 80
#define HW 6400
#define CHW (C_*HW)
#define NCHW (N_*C_*HW)
#define EPSV 1e-5f
#define NBLK 50   // grid.x of gemm (HW/128)

// fp32 scratch
__device__ float g_buf1[NCHW];          // gemm fp32 outputs (h0, y)
__device__ float g_buf2[NCHW];          // fused
__device__ float g_buf3[NCHW];          // gated
__device__ float g_stats1[N_*G_*2];
__device__ float g_stats2[N_*G_*2];
__device__ float g_partials[2 * N_ * G_ * NBLK];
// bf16 hi/lo operand planes
__device__ __nv_bfloat16 g_xh[NCHW], g_xl[NCHW];     // x  (gemm1 B)
__device__ __nv_bfloat16 g_hh[NCHW], g_hl[NCHW];     // h  (gemm2 B)
__device__ __nv_bfloat16 g_dh[NCHW], g_dl[NCHW];     // dw (gemm3 B)
__device__ __nv_bfloat16 g_wh[3*C_*C_], g_wl[3*C_*C_]; // weights

__device__ __forceinline__ uint32_t smem_u32(const void* p) {
    uint32_t a;
    asm("{ .reg .u64 t; cvta.to.shared.u64 t, %1; cvt.u32.u64 %0, t; }"
        : "=r"(a) : "l"(p));
    return a;
}
#define CP_ASYNC16(dst, src) \
    asm volatile("cp.async.cg.shared.global [%0], [%1], 16;" :: "r"(dst), "l"(src))
#define CP_COMMIT() asm volatile("cp.async.commit_group;" ::: "memory")
#define CP_WAIT(n)  asm volatile("cp.async.wait_group %0;" :: "n"(n) : "memory")

// ===========================================================================
// smem layout per stage (bytes):
//   Ahi [128 rows x 40 bf16] = 10240 | Alo 10240 | Bhi [32 x 136 bf16] = 8704 | Blo 8704
// ===========================================================================
#define A_STRIDE 40
#define B_STRIDE 136
#define OFF_ALO  10240
#define OFF_BHI  20480
#define OFF_BLO  29184
#define STAGE_B  37888
#define GEMM_SMEM (2*STAGE_B)

__device__ __forceinline__ void ldsm_x4(uint32_t* r, uint32_t addr) {
    asm volatile("ldmatrix.sync.aligned.m8n8.x4.shared.b16 {%0,%1,%2,%3}, [%4];"
        : "=r"(r[0]), "=r"(r[1]), "=r"(r[2]), "=r"(r[3]) : "r"(addr));
}
__device__ __forceinline__ void ldsm_x2t(uint32_t* r, uint32_t addr) {
    asm volatile("ldmatrix.sync.aligned.m8n8.x2.trans.shared.b16 {%0,%1}, [%2];"
        : "=r"(r[0]), "=r"(r[1]) : "r"(addr));
}
__device__ __forceinline__ void mma_bf16(float* c, const uint32_t* a, const uint32_t* b) {
    asm volatile(
        "mma.sync.aligned.m16n8k16.row.col.f32.bf16.bf16.f32 "
        "{%0,%1,%2,%3}, {%4,%5,%6,%7}, {%8,%9}, {%0,%1,%2,%3};"
        : "+f"(c[0]), "+f"(c[1]), "+f"(c[2]), "+f"(c[3])
        : "r"(a[0]), "r"(a[1]), "r"(a[2]), "r"(a[3]), "r"(b[0]), "r"(b[1]));
}

// issue cp.async copies for one K-chunk into stage st
__device__ __forceinline__ void issue_chunk(
    uint32_t sbase, int tid, int k0, int m0, int n0,
    const __nv_bfloat16* Awh, const __nv_bfloat16* Awl,
    const __nv_bfloat16* Bxh, const __nv_bfloat16* Bxl) {
    // A: 128 rows x 32 bf16 = 4 x 16B segs per row -> 512 copies per plane
#pragma unroll
    for (int j = 0; j < 2; j++) {
        int i = tid + 256 * j;
        int row = i >> 2, seg = i & 3;
        uint32_t dst = sbase + (uint32_t)(row * (A_STRIDE * 2) + seg * 16);
        CP_ASYNC16(dst, Awh + (size_t)(m0 + row) * 256 + k0 + seg * 8);
        CP_ASYNC16(dst + OFF_ALO, Awl + (size_t)(m0 + row) * 256 + k0 + seg * 8);
    }
    // B: 32 rows x 128 bf16 = 16 x 16B segs per row -> 512 copies per plane
#pragma unroll
    for (int j = 0; j < 2; j++) {
        int i = tid + 256 * j;
        int kk = i >> 4, seg = i & 15;
        uint32_t dst = sbase + OFF_BHI + (uint32_t)(kk * (B_STRIDE * 2) + seg * 16);
        CP_ASYNC16(dst, Bxh + (size_t)(k0 + kk) * HW + n0 + seg * 8);
        CP_ASYNC16(dst + (OFF_BLO - OFF_BHI), Bxl + (size_t)(k0 + kk) * HW + n0 + seg * 8);
    }
}

template<int MODE>
__global__ __launch_bounds__(256, 2)
void gemm_mma(const __nv_bfloat16* __restrict__ Awh, const __nv_bfloat16* __restrict__ Awl,
              const __nv_bfloat16* __restrict__ Bxh, const __nv_bfloat16* __restrict__ Bxl,
              float* __restrict__ Y,
              float* __restrict__ partials,
              const float* __restrict__ fusedsrc,
              const float* __restrict__ b_gate) {
    extern __shared__ char smem[];
    __shared__ float sred[8][4][2];
    const uint32_t sb = smem_u32(smem);
    const int tid = threadIdx.x;
    const int lane = tid & 31;
    const int w = tid >> 5;
    const int wm = w & 1;
    const int wn = w >> 1;
    const int n0 = blockIdx.x * 128;
    const int m0 = blockIdx.y * 128;
    const __nv_bfloat16* Bh = Bxh + (size_t)blockIdx.z * CHW;
    const __nv_bfloat16* Bl = Bxl + (size_t)blockIdx.z * CHW;
    float* Yn = Y + (size_t)blockIdx.z * CHW;

    float acc[4][4][4];
#pragma unroll
    for (int i = 0; i < 4; i++)
#pragma unroll
        for (int j = 0; j < 4; j++)
#pragma unroll
            for (int q = 0; q < 4; q++) acc[i][j][q] = 0.f;

    issue_chunk(sb, tid, 0, m0, n0, Awh, Awl, Bh, Bl);
    CP_COMMIT();

    const uint32_t a_lane_off = (uint32_t)((lane & 15) * A_STRIDE + ((lane >> 4) << 3)) * 2;
    const uint32_t b_lane_off = (uint32_t)((lane & 15) * B_STRIDE) * 2;

    for (int ch = 0; ch < 8; ch++) {
        const int st = ch & 1;
        if (ch < 7) {
            issue_chunk(sb + ((ch + 1) & 1) * STAGE_B, tid, (ch + 1) * 32, m0, n0,
                        Awh, Awl, Bh, Bl);
            CP_COMMIT();
            CP_WAIT(1);
        } else {
            CP_WAIT(0);
        }
        __syncthreads();
        {
            const uint32_t SB = sb + st * STAGE_B;
            const uint32_t a_base = SB + (uint32_t)(wm * 64) * (A_STRIDE * 2) + a_lane_off;
#pragma unroll
            for (int ks = 0; ks < 2; ks++) {
                const uint32_t kb = (uint32_t)(ks * 16);
                uint32_t ah[4][4], al[4][4], bh[4][2], bl[4][2];
#pragma unroll
                for (int mt = 0; mt < 4; mt++) {
                    uint32_t ad = a_base + (uint32_t)(mt * 16) * (A_STRIDE * 2) + kb * 2;
                    ldsm_x4(ah[mt], ad);
                    ldsm_x4(al[mt], ad + OFF_ALO);
                }
#pragma unroll
                for (int nt = 0; nt < 4; nt++) {
                    uint32_t bd = SB + OFF_BHI + b_lane_off + kb * (B_STRIDE * 2)
                                  + (uint32_t)(wn * 32 + nt * 8) * 2;
                    ldsm_x2t(bh[nt], bd);
                    ldsm_x2t(bl[nt], bd + (OFF_BLO - OFF_BHI));
                }
#pragma unroll
                for (int mt = 0; mt < 4; mt++)
#pragma unroll
                    for (int nt = 0; nt < 4; nt++) {
                        mma_bf16(acc[mt][nt], ah[mt], bh[nt]);
                        mma_bf16(acc[mt][nt], ah[mt], bl[nt]);
                        mma_bf16(acc[mt][nt], al[mt], bh[nt]);
                    }
            }
        }
        __syncthreads();
    }

    if (MODE == 0) {
        float s[4], s2[4];
#pragma unroll
        for (int mt = 0; mt < 4; mt++) { s[mt] = 0.f; s2[mt] = 0.f; }
#pragma unroll
        for (int mt = 0; mt < 4; mt++) {
            const int r = m0 + wm * 64 + mt * 16 + (lane >> 2);
#pragma unroll
            for (int nt = 0; nt < 4; nt++) {
                const int cc = n0 + wn * 32 + nt * 8 + (lane & 3) * 2;
                float* p = Yn + (size_t)r * HW + cc;
                *(float2*)p = make_float2(acc[mt][nt][0], acc[mt][nt][1]);
                *(float2*)(p + 8 * HW) = make_float2(acc[mt][nt][2], acc[mt][nt][3]);
#pragma unroll
                for (int q = 0; q < 4; q++) {
                    float v = acc[mt][nt][q];
                    s[mt] += v; s2[mt] += v * v;
                }
            }
        }
#pragma unroll
        for (int mt = 0; mt < 4; mt++) {
#pragma unroll
            for (int off = 16; off > 0; off >>= 1) {
                s[mt]  += __shfl_down_sync(0xFFFFFFFFu, s[mt], off);
                s2[mt] += __shfl_down_sync(0xFFFFFFFFu, s2[mt], off);
            }
        }
        __syncthreads();
        if (lane == 0) {
#pragma unroll
            for (int mt = 0; mt < 4; mt++) {
                sred[w][mt][0] = s[mt];
                sred[w][mt][1] = s2[mt];
            }
        }
        __syncthreads();
        if (tid < 8) {
            const int twm = tid >> 2, tmt = tid & 3;
            float S = 0.f, S2 = 0.f;
#pragma unroll
            for (int j = 0; j < 4; j++) {
                S  += sred[twm + 2 * j][tmt][0];
                S2 += sred[twm + 2 * j][tmt][1];
            }
            const int g = blockIdx.y * 8 + twm * 4 + tmt;
            const int ng = blockIdx.z * G_ + g;
            partials[ng * NBLK + blockIdx.x] = S;
            partials[N_ * G_ * NBLK + ng * NBLK + blockIdx.x] = S2;
        }
    } else {
        const float* fn = fusedsrc + (size_t)blockIdx.z * CHW;
#pragma unroll
        for (int mt = 0; mt < 4; mt++) {
            const int r0 = m0 + wm * 64 + mt * 16 + (lane >> 2);
#pragma unroll
            for (int nt = 0; nt < 4; nt++) {
                const int cc = n0 + wn * 32 + nt * 8 + (lane & 3) * 2;
#pragma unroll
                for (int half = 0; half < 2; half++) {
                    const int r = r0 + half * 8;
                    const float bg = b_gate[r];
                    float2 fv = *(const float2*)(fn + (size_t)r * HW + cc);
                    float g0 = 1.f / (1.f + expf(-(acc[mt][nt][half * 2 + 0] + bg)));
                    float g1 = 1.f / (1.f + expf(-(acc[mt][nt][half * 2 + 1] + bg)));
                    *(float2*)(Yn + (size_t)r * HW + cc) =
                        make_float2(fv.x * g0, fv.y * g1);
                }
            }
        }
    }
}

// ---------------------------------------------------------------------------
// fp32 -> bf16 hi/lo split (grid-stride, vectorized)
// ---------------------------------------------------------------------------
__global__ void cvt_split_k(const float* __restrict__ in,
                            __nv_bfloat16* __restrict__ hi,
                            __nv_bfloat16* __restrict__ lo, int n4) {
    int i = blockIdx.x * 256 + threadIdx.x;
    if (i >= n4) return;
    float4 v = *(const float4*)(in + i * 4);
    __nv_bfloat16 hx = __float2bfloat16(v.x), hy = __float2bfloat16(v.y);
    __nv_bfloat16 hz = __float2bfloat16(v.z), hw = __float2bfloat16(v.w);
    __nv_bfloat162 h01(hx, hy), h23(hz, hw);
    __nv_bfloat162 l01(__float2bfloat16(v.x - __bfloat162float(hx)),
                       __float2bfloat16(v.y - __bfloat162float(hy)));
    __nv_bfloat162 l23(__float2bfloat16(v.z - __bfloat162float(hz)),
                       __float2bfloat16(v.w - __bfloat162float(hw)));
    ((__nv_bfloat162*)hi)[i * 2] = h01; ((__nv_bfloat162*)hi)[i * 2 + 1] = h23;
    ((__nv_bfloat162*)lo)[i * 2] = l01; ((__nv_bfloat162*)lo)[i * 2 + 1] = l23;
}

// ---------------------------------------------------------------------------
__global__ void finalize_stats_k(const float* __restrict__ partials,
                                 float* __restrict__ stats) {
    const int ng = threadIdx.x;
    float s = 0.f, s2 = 0.f;
    for (int b = 0; b < NBLK; b++) {
        s  += partials[ng * NBLK + b];
        s2 += partials[N_ * G_ * NBLK + ng * NBLK + b];
    }
    const float M = (float)(CPG * HW);
    float mean = s / M;
    float var = s2 / M - mean * mean;
    stats[ng * 2] = mean;
    stats[ng * 2 + 1] = rsqrtf(var + EPSV);
}

// ---------------------------------------------------------------------------
// GN + SiLU + fused. h written as bf16 hi/lo (GEMM operand), fused fp32.
// ---------------------------------------------------------------------------
__global__ void gn_silu_rowcol_k(const float* __restrict__ X,
                                 const float* __restrict__ stats,
                                 const float* __restrict__ gamma,
                                 const float* __restrict__ beta,
                                 __nv_bfloat16* __restrict__ Hh,
                                 __nv_bfloat16* __restrict__ Hl,
                                 float* __restrict__ F) {
    __shared__ float plane[HW];
    __shared__ float rs[H_], cs[W_];
    const int nc = blockIdx.x;
    const int c = nc & (C_ - 1);
    const int ng = (nc >> 8) * G_ + (c >> 4);
    const float mean = stats[ng * 2];
    const float rstd = stats[ng * 2 + 1];
    const float ga = gamma[c];
    const float be = beta[c];
    const float* base = X + (size_t)nc * HW;
    __nv_bfloat16* hh = Hh + (size_t)nc * HW;
    __nv_bfloat16* hl = Hl + (size_t)nc * HW;
    float* fb = F + (size_t)nc * HW;

    for (int i = threadIdx.x; i < HW; i += 256) {
        float v = base[i];
        v = (v - mean) * rstd * ga + be;
        float sg = 1.f / (1.f + expf(-v));
        v = v * sg;
        plane[i] = v;
        __nv_bfloat16 h = __float2bfloat16(v);
        hh[i] = h;
        hl[i] = __float2bfloat16(v - __bfloat162float(h));
    }
    __syncthreads();
    if (threadIdx.x < H_) {
        const int y = threadIdx.x;
        float s = 0.f;
#pragma unroll 8
        for (int x = 0; x < W_; x++) s += plane[y * W_ + x];
        rs[y] = s;
    } else if (threadIdx.x < H_ + W_) {
        const int x = threadIdx.x - H_;
        float s = 0.f;
#pragma unroll 8
        for (int y = 0; y < H_; y++) s += plane[y * W_ + x];
        cs[x] = s;
    }
    __syncthreads();
    for (int i = threadIdx.x; i < HW; i += 256) {
        const int y = i / W_;
        const int x = i - y * W_;
        fb[i] = 0.25f * (rs[y] + cs[x] + 2.f * plane[i]);
    }
}

// ---------------------------------------------------------------------------
// depthwise 3x3 — plane in smem; output as bf16 hi/lo (GEMM operand)
// ---------------------------------------------------------------------------
__global__ void dw3x3_k(const float* __restrict__ in,
                        const float* __restrict__ wdw,
                        __nv_bfloat16* __restrict__ Oh,
                        __nv_bfloat16* __restrict__ Ol) {
    __shared__ float pl[HW];
    const int nc = blockIdx.x;
    const int c = nc & (C_ - 1);
    float wr[9];
#pragma unroll
    for (int q = 0; q < 9; q++) wr[q] = __ldg(wdw + c * 9 + q);
    const float* p = in + (size_t)nc * HW;
    __nv_bfloat16* oh = Oh + (size_t)nc * HW;
    __nv_bfloat16* ol = Ol + (size_t)nc * HW;
    for (int i = threadIdx.x; i < HW; i += 256) pl[i] = p[i];
    __syncthreads();
    for (int i = threadIdx.x; i < HW; i += 256) {
        const int y = i / W_;
        const int x = i - y * W_;
        float s = 0.f;
#pragma unroll
        for (int dy = -1; dy <= 1; dy++) {
            const int yy = y + dy;
            if ((unsigned)yy >= H_) continue;
#pragma unroll
            for (int dx = -1; dx <= 1; dx++) {
                const int xx = x + dx;
                if ((unsigned)xx >= W_) continue;
                s += wr[(dy + 1) * 3 + (dx + 1)] * pl[yy * W_ + xx];
            }
        }
        __nv_bfloat16 h = __float2bfloat16(s);
        oh[i] = h;
        ol[i] = __float2bfloat16(s - __bfloat162float(h));
    }
}

// ---------------------------------------------------------------------------
__global__ void gn_silu_out_k(const float* __restrict__ X,
                              const float* __restrict__ stats,
                              const float* __restrict__ gamma,
                              const float* __restrict__ beta,
                              float* __restrict__ out) {
    const int idx = blockIdx.x * 256 + threadIdx.x;
    const int nc = idx / HW;
    const int c = nc & (C_ - 1);
    const int ng = (nc >> 8) * G_ + (c >> 4);
    float v = X[idx];
    v = (v - stats[ng * 2]) * stats[ng * 2 + 1] * gamma[c] + beta[c];
    float sg = 1.f / (1.f + expf(-v));
    out[idx] = v * sg;
}

// ---------------------------------------------------------------------------
extern "C" void kernel_launch(void* const* d_in, const int* in_sizes, int n_in,
                              void* d_out, int out_size) {
    const float* x      = (const float*)d_in[0];
    const float* w_pre  = (const float*)d_in[1];
    const float* g1     = (const float*)d_in[2];
    const float* b1     = (const float*)d_in[3];
    const float* w_gate = (const float*)d_in[4];
    const float* b_gate = (const float*)d_in[5];
    const float* w_dw   = (const float*)d_in[6];
    const float* w_pw   = (const float*)d_in[7];
    const float* g2     = (const float*)d_in[8];
    const float* b2     = (const float*)d_in[9];
    float* out = (float*)d_out;

    float *buf1, *buf2, *buf3, *stats1, *stats2, *partials;
    __nv_bfloat16 *xh, *xl, *hh, *hl, *dh, *dl, *wh, *wl;
    cudaGetSymbolAddress((void**)&buf1, g_buf1);
    cudaGetSymbolAddress((void**)&buf2, g_buf2);
    cudaGetSymbolAddress((void**)&buf3, g_buf3);
    cudaGetSymbolAddress((void**)&stats1, g_stats1);
    cudaGetSymbolAddress((void**)&stats2, g_stats2);
    cudaGetSymbolAddress((void**)&partials, g_partials);
    cudaGetSymbolAddress((void**)&xh, g_xh);
    cudaGetSymbolAddress((void**)&xl, g_xl);
    cudaGetSymbolAddress((void**)&hh, g_hh);
    cudaGetSymbolAddress((void**)&hl, g_hl);
    cudaGetSymbolAddress((void**)&dh, g_dh);
    cudaGetSymbolAddress((void**)&dl, g_dl);
    cudaGetSymbolAddress((void**)&wh, g_wh);
    cudaGetSymbolAddress((void**)&wl, g_wl);

    cudaFuncSetAttribute(gemm_mma<0>, cudaFuncAttributeMaxDynamicSharedMemorySize, GEMM_SMEM);
    cudaFuncSetAttribute(gemm_mma<1>, cudaFuncAttributeMaxDynamicSharedMemorySize, GEMM_SMEM);

    dim3 ggrid(NBLK, 2, N_);
    const int eblocks = NCHW / 256;

    // 0) operand conversion
    cvt_split_k<<<(C_*C_/4 + 255)/256, 256>>>(w_pre,  wh,            wl,            C_*C_/4);
    cvt_split_k<<<(C_*C_/4 + 255)/256, 256>>>(w_gate, wh + C_*C_,    wl + C_*C_,    C_*C_/4);
    cvt_split_k<<<(C_*C_/4 + 255)/256, 256>>>(w_pw,   wh + 2*C_*C_,  wl + 2*C_*C_,  C_*C_/4);
    cvt_split_k<<<NCHW/4/256, 256>>>(x, xh, xl, NCHW/4);

    // 1) h0 = conv1x1(x, w_pre) + GN1 partial stats
    gemm_mma<0><<<ggrid, 256, GEMM_SMEM>>>(wh, wl, xh, xl, buf1, partials, nullptr, nullptr);
    finalize_stats_k<<<1, 128>>>(partials, stats1);
    // 2) h = silu(gn(h0)) -> bf16 hi/lo + fused -> buf2
    gn_silu_rowcol_k<<<N_ * C_, 256>>>(buf1, stats1, g1, b1, hh, hl, buf2);
    // 3) gated = fused * sigmoid(conv1x1(h,w_gate)+b) -> buf3
    gemm_mma<1><<<ggrid, 256, GEMM_SMEM>>>(wh + C_*C_, wl + C_*C_, hh, hl, buf3, nullptr, buf2, b_gate);
    // 4) depthwise 3x3: buf3 -> bf16 hi/lo
    dw3x3_k<<<N_ * C_, 256>>>(buf3, w_dw, dh, dl);
    // 5) y = conv1x1(dw, w_pw) + GN2 partial stats
    gemm_mma<0><<<ggrid, 256, GEMM_SMEM>>>(wh + 2*C_*C_, wl + 2*C_*C_, dh, dl, buf1, partials, nullptr, nullptr);
    finalize_stats_k<<<1, 128>>>(partials, stats2);
    // 6) out = silu(gn(y))
    gn_silu_out_k<<<eblocks, 256>>>(buf1, stats2, g2, b2, out);
}

// round 7
// speedup vs baseline: 2.3598x; 1.2502x over previous
#include <cuda_runtime.h>
#include <cuda_fp16.h>
#include <math.h>
#include <cstdint>

#define C_ 256
#define G_ 16
#define CPG 16
#define N_ 8
#define H_ 80
#define W_ 80
#define HW 6400
#define CHW (C_*HW)
#define NCHW (N_*C_*HW)
#define EPSV 1e-5f
#define NBLK 50   // grid.x of gemm (HW/128)

// fp32 scratch
__device__ float g_buf1[NCHW];          // gemm fp32 outputs (h0, y)
__device__ float g_buf2[NCHW];          // fused
__device__ float g_buf3[NCHW];          // gated
__device__ float g_stats1[N_*G_*2];
__device__ float g_stats2[N_*G_*2];
__device__ float g_partials[2 * N_ * G_ * NBLK];
// fp16 operand planes (B side single, weights hi/lo)
__device__ __half g_xh[NCHW];           // x   (gemm1 B)
__device__ __half g_hh[NCHW];           // h   (gemm2 B)
__device__ __half g_dh[NCHW];           // dw  (gemm3 B)
__device__ __half g_wh[3*C_*C_], g_wl[3*C_*C_];

__device__ __forceinline__ uint32_t smem_u32(const void* p) {
    uint32_t a;
    asm("{ .reg .u64 t; cvta.to.shared.u64 t, %1; cvt.u32.u64 %0, t; }"
        : "=r"(a) : "l"(p));
    return a;
}
#define CP_ASYNC16(dst, src) \
    asm volatile("cp.async.cg.shared.global [%0], [%1], 16;" :: "r"(dst), "l"(src))
#define CP_COMMIT() asm volatile("cp.async.commit_group;" ::: "memory")
#define CP_WAIT(n)  asm volatile("cp.async.wait_group %0;" :: "n"(n) : "memory")

// ===========================================================================
// smem per stage: Whi [128 x 40 half] = 10240 | Wlo 10240 | B [32 x 136 half] = 8704
// 3 stages.
// ===========================================================================
#define A_STRIDE 40
#define B_STRIDE 136
#define OFF_ALO  10240
#define OFF_B    20480
#define STAGE_B  29184
#define NSTAGE   3
#define GEMM_SMEM (NSTAGE*STAGE_B)

__device__ __forceinline__ void ldsm_x4(uint32_t* r, uint32_t addr) {
    asm volatile("ldmatrix.sync.aligned.m8n8.x4.shared.b16 {%0,%1,%2,%3}, [%4];"
        : "=r"(r[0]), "=r"(r[1]), "=r"(r[2]), "=r"(r[3]) : "r"(addr));
}
__device__ __forceinline__ void ldsm_x2t(uint32_t* r, uint32_t addr) {
    asm volatile("ldmatrix.sync.aligned.m8n8.x2.trans.shared.b16 {%0,%1}, [%2];"
        : "=r"(r[0]), "=r"(r[1]) : "r"(addr));
}
__device__ __forceinline__ void mma_f16(float* c, const uint32_t* a, const uint32_t* b) {
    asm volatile(
        "mma.sync.aligned.m16n8k16.row.col.f32.f16.f16.f32 "
        "{%0,%1,%2,%3}, {%4,%5,%6,%7}, {%8,%9}, {%0,%1,%2,%3};"
        : "+f"(c[0]), "+f"(c[1]), "+f"(c[2]), "+f"(c[3])
        : "r"(a[0]), "r"(a[1]), "r"(a[2]), "r"(a[3]), "r"(b[0]), "r"(b[1]));
}

__device__ __forceinline__ void issue_chunk(
    uint32_t sbase, int tid, int k0, int m0, int n0,
    const __half* Wh, const __half* Wl, const __half* Bx) {
    // A: 128 rows x 32 halfs -> 4 x 16B per row, two planes
#pragma unroll
    for (int j = 0; j < 2; j++) {
        int i = tid + 256 * j;
        int row = i >> 2, seg = i & 3;
        uint32_t dst = sbase + (uint32_t)(row * (A_STRIDE * 2) + seg * 16);
        const __half* s = Wh + (size_t)(m0 + row) * 256 + k0 + seg * 8;
        CP_ASYNC16(dst, s);
        CP_ASYNC16(dst + OFF_ALO, Wl + (size_t)(m0 + row) * 256 + k0 + seg * 8);
    }
    // B: 32 rows x 128 halfs -> 16 x 16B per row, single plane
#pragma unroll
    for (int j = 0; j < 2; j++) {
        int i = tid + 256 * j;
        int kk = i >> 4, seg = i & 15;
        uint32_t dst = sbase + OFF_B + (uint32_t)(kk * (B_STRIDE * 2) + seg * 16);
        CP_ASYNC16(dst, Bx + (size_t)(k0 + kk) * HW + n0 + seg * 8);
    }
}

template<int MODE>
__global__ __launch_bounds__(256, 2)
void gemm_mma(const __half* __restrict__ Wh, const __half* __restrict__ Wl,
              const __half* __restrict__ Bx,
              float* __restrict__ Y,
              float* __restrict__ partials,
              const float* __restrict__ fusedsrc,
              const float* __restrict__ b_gate) {
    extern __shared__ char smem[];
    __shared__ float sred[8][4][2];
    const uint32_t sb = smem_u32(smem);
    const int tid = threadIdx.x;
    const int lane = tid & 31;
    const int w = tid >> 5;
    const int wm = w & 1;
    const int wn = w >> 1;
    const int n0 = blockIdx.x * 128;
    const int m0 = blockIdx.y * 128;
    const __half* Bn = Bx + (size_t)blockIdx.z * CHW;
    float* Yn = Y + (size_t)blockIdx.z * CHW;

    float acc[4][4][4];
#pragma unroll
    for (int i = 0; i < 4; i++)
#pragma unroll
        for (int j = 0; j < 4; j++)
#pragma unroll
            for (int q = 0; q < 4; q++) acc[i][j][q] = 0.f;

    issue_chunk(sb, tid, 0, m0, n0, Wh, Wl, Bn);
    CP_COMMIT();
    issue_chunk(sb + STAGE_B, tid, 32, m0, n0, Wh, Wl, Bn);
    CP_COMMIT();

    const uint32_t a_lane_off = (uint32_t)((lane & 15) * A_STRIDE + ((lane >> 4) << 3)) * 2;
    const uint32_t b_lane_off = (uint32_t)((lane & 15) * B_STRIDE) * 2;

    for (int ch = 0; ch < 8; ch++) {
        const int st = ch % NSTAGE;
        if (ch < 7) { CP_WAIT(1); } else { CP_WAIT(0); }
        __syncthreads();
        {
            const uint32_t SB = sb + st * STAGE_B;
            const uint32_t a_base = SB + (uint32_t)(wm * 64) * (A_STRIDE * 2) + a_lane_off;
#pragma unroll
            for (int ks = 0; ks < 2; ks++) {
                const uint32_t kb = (uint32_t)(ks * 16);
                uint32_t ah[4][4], al[4][4], bh[4][2];
#pragma unroll
                for (int mt = 0; mt < 4; mt++) {
                    uint32_t ad = a_base + (uint32_t)(mt * 16) * (A_STRIDE * 2) + kb * 2;
                    ldsm_x4(ah[mt], ad);
                    ldsm_x4(al[mt], ad + OFF_ALO);
                }
#pragma unroll
                for (int nt = 0; nt < 4; nt++) {
                    uint32_t bd = SB + OFF_B + b_lane_off + kb * (B_STRIDE * 2)
                                  + (uint32_t)(wn * 32 + nt * 8) * 2;
                    ldsm_x2t(bh[nt], bd);
                }
#pragma unroll
                for (int mt = 0; mt < 4; mt++)
#pragma unroll
                    for (int nt = 0; nt < 4; nt++) {
                        mma_f16(acc[mt][nt], ah[mt], bh[nt]);
                        mma_f16(acc[mt][nt], al[mt], bh[nt]);
                    }
            }
        }
        if (ch < 6) {
            issue_chunk(sb + ((ch + 2) % NSTAGE) * STAGE_B, tid, (ch + 2) * 32, m0, n0,
                        Wh, Wl, Bn);
            CP_COMMIT();
        }
    }

    if (MODE == 0) {
        float s[4], s2[4];
#pragma unroll
        for (int mt = 0; mt < 4; mt++) { s[mt] = 0.f; s2[mt] = 0.f; }
#pragma unroll
        for (int mt = 0; mt < 4; mt++) {
            const int r = m0 + wm * 64 + mt * 16 + (lane >> 2);
#pragma unroll
            for (int nt = 0; nt < 4; nt++) {
                const int cc = n0 + wn * 32 + nt * 8 + (lane & 3) * 2;
                float* p = Yn + (size_t)r * HW + cc;
                *(float2*)p = make_float2(acc[mt][nt][0], acc[mt][nt][1]);
                *(float2*)(p + 8 * HW) = make_float2(acc[mt][nt][2], acc[mt][nt][3]);
#pragma unroll
                for (int q = 0; q < 4; q++) {
                    float v = acc[mt][nt][q];
                    s[mt] += v; s2[mt] += v * v;
                }
            }
        }
#pragma unroll
        for (int mt = 0; mt < 4; mt++) {
#pragma unroll
            for (int off = 16; off > 0; off >>= 1) {
                s[mt]  += __shfl_down_sync(0xFFFFFFFFu, s[mt], off);
                s2[mt] += __shfl_down_sync(0xFFFFFFFFu, s2[mt], off);
            }
        }
        __syncthreads();
        if (lane == 0) {
#pragma unroll
            for (int mt = 0; mt < 4; mt++) {
                sred[w][mt][0] = s[mt];
                sred[w][mt][1] = s2[mt];
            }
        }
        __syncthreads();
        if (tid < 8) {
            const int twm = tid >> 2, tmt = tid & 3;
            float S = 0.f, S2 = 0.f;
#pragma unroll
            for (int j = 0; j < 4; j++) {
                S  += sred[twm + 2 * j][tmt][0];
                S2 += sred[twm + 2 * j][tmt][1];
            }
            const int g = blockIdx.y * 8 + twm * 4 + tmt;
            const int ng = blockIdx.z * G_ + g;
            partials[ng * NBLK + blockIdx.x] = S;
            partials[N_ * G_ * NBLK + ng * NBLK + blockIdx.x] = S2;
        }
    } else {
        const float* fn = fusedsrc + (size_t)blockIdx.z * CHW;
#pragma unroll
        for (int mt = 0; mt < 4; mt++) {
            const int r0 = m0 + wm * 64 + mt * 16 + (lane >> 2);
#pragma unroll
            for (int nt = 0; nt < 4; nt++) {
                const int cc = n0 + wn * 32 + nt * 8 + (lane & 3) * 2;
#pragma unroll
                for (int half = 0; half < 2; half++) {
                    const int r = r0 + half * 8;
                    const float bg = b_gate[r];
                    float2 fv = *(const float2*)(fn + (size_t)r * HW + cc);
                    float g0 = 1.f / (1.f + expf(-(acc[mt][nt][half * 2 + 0] + bg)));
                    float g1 = 1.f / (1.f + expf(-(acc[mt][nt][half * 2 + 1] + bg)));
                    *(float2*)(Yn + (size_t)r * HW + cc) =
                        make_float2(fv.x * g0, fv.y * g1);
                }
            }
        }
    }
}

// ---------------------------------------------------------------------------
// fp32 -> fp16 hi/lo (weights)
// ---------------------------------------------------------------------------
__global__ void cvt_w_k(const float* __restrict__ in,
                        __half* __restrict__ hi, __half* __restrict__ lo, int n) {
    int i = blockIdx.x * 256 + threadIdx.x;
    if (i >= n) return;
    float v = in[i];
    __half h = __float2half(v);
    hi[i] = h;
    lo[i] = __float2half(v - __half2float(h));
}

// fp32 -> fp16 single (activations), vectorized
__global__ void cvt_x_k(const float* __restrict__ in, __half* __restrict__ o, int n4) {
    int i = blockIdx.x * 256 + threadIdx.x;
    if (i >= n4) return;
    float4 v = *(const float4*)(in + i * 4);
    __half2 a(__float2half(v.x), __float2half(v.y));
    __half2 b(__float2half(v.z), __float2half(v.w));
    uint2 pk = make_uint2(*(uint32_t*)&a, *(uint32_t*)&b);
    *(uint2*)(o + i * 4) = pk;
}

// ---------------------------------------------------------------------------
__global__ void finalize_stats_k(const float* __restrict__ partials,
                                 float* __restrict__ stats) {
    const int ng = threadIdx.x;
    float s = 0.f, s2 = 0.f;
    for (int b = 0; b < NBLK; b++) {
        s  += partials[ng * NBLK + b];
        s2 += partials[N_ * G_ * NBLK + ng * NBLK + b];
    }
    const float M = (float)(CPG * HW);
    float mean = s / M;
    float var = s2 / M - mean * mean;
    stats[ng * 2] = mean;
    stats[ng * 2 + 1] = rsqrtf(var + EPSV);
}

// ---------------------------------------------------------------------------
// GN + SiLU + fused. h written fp16 (GEMM operand), fused fp32.
// ---------------------------------------------------------------------------
__global__ void gn_silu_rowcol_k(const float* __restrict__ X,
                                 const float* __restrict__ stats,
                                 const float* __restrict__ gamma,
                                 const float* __restrict__ beta,
                                 __half* __restrict__ Hh,
                                 float* __restrict__ F) {
    __shared__ float plane[HW];
    __shared__ float rs[H_], cs[W_];
    const int nc = blockIdx.x;
    const int c = nc & (C_ - 1);
    const int ng = (nc >> 8) * G_ + (c >> 4);
    const float mean = stats[ng * 2];
    const float rstd = stats[ng * 2 + 1];
    const float ga = gamma[c];
    const float be = beta[c];
    const float* base = X + (size_t)nc * HW;
    __half* hh = Hh + (size_t)nc * HW;
    float* fb = F + (size_t)nc * HW;

    for (int i = threadIdx.x; i < HW; i += 256) {
        float v = base[i];
        v = (v - mean) * rstd * ga + be;
        float sg = 1.f / (1.f + expf(-v));
        v = v * sg;
        plane[i] = v;
        hh[i] = __float2half(v);
    }
    __syncthreads();
    if (threadIdx.x < H_) {
        const int y = threadIdx.x;
        float s = 0.f;
#pragma unroll 8
        for (int x = 0; x < W_; x++) s += plane[y * W_ + x];
        rs[y] = s;
    } else if (threadIdx.x < H_ + W_) {
        const int x = threadIdx.x - H_;
        float s = 0.f;
#pragma unroll 8
        for (int y = 0; y < H_; y++) s += plane[y * W_ + x];
        cs[x] = s;
    }
    __syncthreads();
    for (int i = threadIdx.x; i < HW; i += 256) {
        const int y = i / W_;
        const int x = i - y * W_;
        fb[i] = 0.25f * (rs[y] + cs[x] + 2.f * plane[i]);
    }
}

// ---------------------------------------------------------------------------
// depthwise 3x3 — plane in smem; output fp16 (GEMM operand)
// ---------------------------------------------------------------------------
__global__ void dw3x3_k(const float* __restrict__ in,
                        const float* __restrict__ wdw,
                        __half* __restrict__ Oh) {
    __shared__ float pl[HW];
    const int nc = blockIdx.x;
    const int c = nc & (C_ - 1);
    float wr[9];
#pragma unroll
    for (int q = 0; q < 9; q++) wr[q] = __ldg(wdw + c * 9 + q);
    const float* p = in + (size_t)nc * HW;
    __half* oh = Oh + (size_t)nc * HW;
    for (int i = threadIdx.x; i < HW; i += 256) pl[i] = p[i];
    __syncthreads();
    for (int i = threadIdx.x; i < HW; i += 256) {
        const int y = i / W_;
        const int x = i - y * W_;
        float s = 0.f;
#pragma unroll
        for (int dy = -1; dy <= 1; dy++) {
            const int yy = y + dy;
            if ((unsigned)yy >= H_) continue;
#pragma unroll
            for (int dx = -1; dx <= 1; dx++) {
                const int xx = x + dx;
                if ((unsigned)xx >= W_) continue;
                s += wr[(dy + 1) * 3 + (dx + 1)] * pl[yy * W_ + xx];
            }
        }
        oh[i] = __float2half(s);
    }
}

// ---------------------------------------------------------------------------
__global__ void gn_silu_out_k(const float* __restrict__ X,
                              const float* __restrict__ stats,
                              const float* __restrict__ gamma,
                              const float* __restrict__ beta,
                              float* __restrict__ out) {
    const int idx = blockIdx.x * 256 + threadIdx.x;
    const int nc = idx / HW;
    const int c = nc & (C_ - 1);
    const int ng = (nc >> 8) * G_ + (c >> 4);
    float v = X[idx];
    v = (v - stats[ng * 2]) * stats[ng * 2 + 1] * gamma[c] + beta[c];
    float sg = 1.f / (1.f + expf(-v));
    out[idx] = v * sg;
}

// ---------------------------------------------------------------------------
extern "C" void kernel_launch(void* const* d_in, const int* in_sizes, int n_in,
                              void* d_out, int out_size) {
    const float* x      = (const float*)d_in[0];
    const float* w_pre  = (const float*)d_in[1];
    const float* g1     = (const float*)d_in[2];
    const float* b1     = (const float*)d_in[3];
    const float* w_gate = (const float*)d_in[4];
    const float* b_gate = (const float*)d_in[5];
    const float* w_dw   = (const float*)d_in[6];
    const float* w_pw   = (const float*)d_in[7];
    const float* g2     = (const float*)d_in[8];
    const float* b2     = (const float*)d_in[9];
    float* out = (float*)d_out;

    float *buf1, *buf2, *buf3, *stats1, *stats2, *partials;
    __half *xh, *hh, *dh, *wh, *wl;
    cudaGetSymbolAddress((void**)&buf1, g_buf1);
    cudaGetSymbolAddress((void**)&buf2, g_buf2);
    cudaGetSymbolAddress((void**)&buf3, g_buf3);
    cudaGetSymbolAddress((void**)&stats1, g_stats1);
    cudaGetSymbolAddress((void**)&stats2, g_stats2);
    cudaGetSymbolAddress((void**)&partials, g_partials);
    cudaGetSymbolAddress((void**)&xh, g_xh);
    cudaGetSymbolAddress((void**)&hh, g_hh);
    cudaGetSymbolAddress((void**)&dh, g_dh);
    cudaGetSymbolAddress((void**)&wh, g_wh);
    cudaGetSymbolAddress((void**)&wl, g_wl);

    cudaFuncSetAttribute(gemm_mma<0>, cudaFuncAttributeMaxDynamicSharedMemorySize, GEMM_SMEM);
    cudaFuncSetAttribute(gemm_mma<1>, cudaFuncAttributeMaxDynamicSharedMemorySize, GEMM_SMEM);

    dim3 ggrid(NBLK, 2, N_);
    const int eblocks = NCHW / 256;

    // 0) operand conversion
    cvt_w_k<<<C_*C_/256, 256>>>(w_pre,  wh,           wl,           C_*C_);
    cvt_w_k<<<C_*C_/256, 256>>>(w_gate, wh + C_*C_,   wl + C_*C_,   C_*C_);
    cvt_w_k<<<C_*C_/256, 256>>>(w_pw,   wh + 2*C_*C_, wl + 2*C_*C_, C_*C_);
    cvt_x_k<<<NCHW/4/256, 256>>>(x, xh, NCHW/4);

    // 1) h0 = conv1x1(x, w_pre) + GN1 partial stats
    gemm_mma<0><<<ggrid, 256, GEMM_SMEM>>>(wh, wl, xh, buf1, partials, nullptr, nullptr);
    finalize_stats_k<<<1, 128>>>(partials, stats1);
    // 2) h = silu(gn(h0)) -> fp16 + fused -> buf2
    gn_silu_rowcol_k<<<N_ * C_, 256>>>(buf1, stats1, g1, b1, hh, buf2);
    // 3) gated = fused * sigmoid(conv1x1(h,w_gate)+b) -> buf3
    gemm_mma<1><<<ggrid, 256, GEMM_SMEM>>>(wh + C_*C_, wl + C_*C_, hh, buf3, nullptr, buf2, b_gate);
    // 4) depthwise 3x3: buf3 -> fp16
    dw3x3_k<<<N_ * C_, 256>>>(buf3, w_dw, dh);
    // 5) y = conv1x1(dw, w_pw) + GN2 partial stats
    gemm_mma<0><<<ggrid, 256, GEMM_SMEM>>>(wh + 2*C_*C_, wl + 2*C_*C_, dh, buf1, partials, nullptr, nullptr);
    finalize_stats_k<<<1, 128>>>(partials, stats2);
    // 6) out = silu(gn(y))
    gn_silu_out_k<<<eblocks, 256>>>(buf1, stats2, g2, b2, out);
}

// round 8
// speedup vs baseline: 2.7816x; 1.1787x over previous
#include <cuda_runtime.h>
#include <cuda_fp16.h>
#include <math.h>
#include <cstdint>

#define C_ 256
#define G_ 16
#define CPG 16
#define N_ 8
#define H_ 80
#define W_ 80
#define HW 6400
#define CHW (C_*HW)
#define NCHW (N_*C_*HW)
#define EPSV 1e-5f
#define NBLK 50   // grid.x of gemm (HW/128)

// fp32 scratch
__device__ float g_buf1[NCHW];          // gemm fp32 outputs (h0, y)
__device__ float g_buf2[NCHW];          // fused
__device__ float g_buf3[NCHW];          // gated
__device__ float g_stats1[N_*G_*2];
__device__ float g_stats2[N_*G_*2];
__device__ float g_partials[2 * N_ * G_ * NBLK];
// fp16 operand planes
__device__ __half g_xh[NCHW];           // x   (gemm1 B)
__device__ __half g_hh[NCHW];           // h   (gemm2 B)
__device__ __half g_dh[NCHW];           // dw  (gemm3 B)
__device__ __half g_wh[3*C_*C_];        // weights fp16

__device__ __forceinline__ uint32_t smem_u32(const void* p) {
    uint32_t a;
    asm("{ .reg .u64 t; cvta.to.shared.u64 t, %1; cvt.u32.u64 %0, t; }"
        : "=r"(a) : "l"(p));
    return a;
}
#define CP_ASYNC16(dst, src) \
    asm volatile("cp.async.cg.shared.global [%0], [%1], 16;" :: "r"(dst), "l"(src))
#define CP_COMMIT() asm volatile("cp.async.commit_group;" ::: "memory")
#define CP_WAIT(n)  asm volatile("cp.async.wait_group %0;" :: "n"(n) : "memory")

// ===========================================================================
// smem: A resident [128 rows x 264 halfs] = 67584 B, then B ring 3 x [32 x 136 halfs]
// ===========================================================================
#define A_STRIDE 264              // halfs per A row (256 + 8 pad)
#define A_BYTES  (128*A_STRIDE*2) // 67584
#define B_STRIDE 136
#define B_STAGE  (32*B_STRIDE*2)  // 8704
#define NSTAGE   3
#define GEMM_SMEM (A_BYTES + NSTAGE*B_STAGE)

__device__ __forceinline__ void ldsm_x4(uint32_t* r, uint32_t addr) {
    asm volatile("ldmatrix.sync.aligned.m8n8.x4.shared.b16 {%0,%1,%2,%3}, [%4];"
        : "=r"(r[0]), "=r"(r[1]), "=r"(r[2]), "=r"(r[3]) : "r"(addr));
}
__device__ __forceinline__ void ldsm_x2t(uint32_t* r, uint32_t addr) {
    asm volatile("ldmatrix.sync.aligned.m8n8.x2.trans.shared.b16 {%0,%1}, [%2];"
        : "=r"(r[0]), "=r"(r[1]) : "r"(addr));
}
__device__ __forceinline__ void mma_f16(float* c, const uint32_t* a, const uint32_t* b) {
    asm volatile(
        "mma.sync.aligned.m16n8k16.row.col.f32.f16.f16.f32 "
        "{%0,%1,%2,%3}, {%4,%5,%6,%7}, {%8,%9}, {%0,%1,%2,%3};"
        : "+f"(c[0]), "+f"(c[1]), "+f"(c[2]), "+f"(c[3])
        : "r"(a[0]), "r"(a[1]), "r"(a[2]), "r"(a[3]), "r"(b[0]), "r"(b[1]));
}

// B chunk: 32 k-rows x 128 n halfs -> 512 x 16B copies (2 per thread)
__device__ __forceinline__ void issue_b(uint32_t sbase, int tid, int k0, int n0,
                                        const __half* Bx) {
#pragma unroll
    for (int j = 0; j < 2; j++) {
        int i = tid + 256 * j;
        int kk = i >> 4, seg = i & 15;
        uint32_t dst = sbase + (uint32_t)(kk * (B_STRIDE * 2) + seg * 16);
        CP_ASYNC16(dst, Bx + (size_t)(k0 + kk) * HW + n0 + seg * 8);
    }
}

template<int MODE>
__global__ __launch_bounds__(256, 2)
void gemm_mma(const __half* __restrict__ Wh, const __half* __restrict__ Bx,
              float* __restrict__ Y,
              float* __restrict__ partials,
              const float* __restrict__ fusedsrc,
              const float* __restrict__ b_gate) {
    extern __shared__ char smem[];
    __shared__ float sred[8][4][2];
    const uint32_t sb = smem_u32(smem);
    const uint32_t bb = sb + A_BYTES;
    const int tid = threadIdx.x;
    const int lane = tid & 31;
    const int w = tid >> 5;
    const int wm = w & 1;
    const int wn = w >> 1;
    const int n0 = blockIdx.x * 128;
    const int m0 = blockIdx.y * 128;
    const __half* Bn = Bx + (size_t)blockIdx.z * CHW;
    float* Yn = Y + (size_t)blockIdx.z * CHW;

    float acc[4][4][4];
#pragma unroll
    for (int i = 0; i < 4; i++)
#pragma unroll
        for (int j = 0; j < 4; j++)
#pragma unroll
            for (int q = 0; q < 4; q++) acc[i][j][q] = 0.f;

    // A resident: 128 rows x 256 halfs = 4096 x 16B copies (16 per thread)
#pragma unroll
    for (int j = 0; j < 16; j++) {
        int i = tid + 256 * j;
        int row = i >> 5, seg = i & 31;
        uint32_t dst = sb + (uint32_t)(row * (A_STRIDE * 2) + seg * 16);
        CP_ASYNC16(dst, Wh + (size_t)(m0 + row) * 256 + seg * 8);
    }
    issue_b(bb, tid, 0, n0, Bn);
    CP_COMMIT();                                   // G0 = A + B0
    issue_b(bb + B_STAGE, tid, 32, n0, Bn);
    CP_COMMIT();                                   // G1 = B1

    const uint32_t a_lane_off = (uint32_t)((lane & 15) * A_STRIDE + ((lane >> 4) << 3)) * 2;
    const uint32_t b_lane_off = (uint32_t)((lane & 15) * B_STRIDE) * 2;

    for (int ch = 0; ch < 8; ch++) {
        const int st = ch % NSTAGE;
        if (ch < 7) { CP_WAIT(1); } else { CP_WAIT(0); }
        __syncthreads();
        {
            const uint32_t a_chunk = sb + (uint32_t)(wm * 64) * (A_STRIDE * 2)
                                     + a_lane_off + (uint32_t)(ch * 32) * 2;
            const uint32_t SBB = bb + st * B_STAGE;
#pragma unroll
            for (int ks = 0; ks < 2; ks++) {
                const uint32_t kb = (uint32_t)(ks * 16);
                uint32_t ah[4][4], bh[4][2];
#pragma unroll
                for (int mt = 0; mt < 4; mt++) {
                    ldsm_x4(ah[mt], a_chunk + (uint32_t)(mt * 16) * (A_STRIDE * 2) + kb * 2);
                }
#pragma unroll
                for (int nt = 0; nt < 4; nt++) {
                    ldsm_x2t(bh[nt], SBB + b_lane_off + kb * (B_STRIDE * 2)
                                     + (uint32_t)(wn * 32 + nt * 8) * 2);
                }
#pragma unroll
                for (int mt = 0; mt < 4; mt++)
#pragma unroll
                    for (int nt = 0; nt < 4; nt++)
                        mma_f16(acc[mt][nt], ah[mt], bh[nt]);
            }
        }
        if (ch < 6) {
            issue_b(bb + ((ch + 2) % NSTAGE) * B_STAGE, tid, (ch + 2) * 32, n0, Bn);
            CP_COMMIT();
        }
    }

    if (MODE == 0) {
        float s[4], s2[4];
#pragma unroll
        for (int mt = 0; mt < 4; mt++) { s[mt] = 0.f; s2[mt] = 0.f; }
#pragma unroll
        for (int mt = 0; mt < 4; mt++) {
            const int r = m0 + wm * 64 + mt * 16 + (lane >> 2);
#pragma unroll
            for (int nt = 0; nt < 4; nt++) {
                const int cc = n0 + wn * 32 + nt * 8 + (lane & 3) * 2;
                float* p = Yn + (size_t)r * HW + cc;
                *(float2*)p = make_float2(acc[mt][nt][0], acc[mt][nt][1]);
                *(float2*)(p + 8 * HW) = make_float2(acc[mt][nt][2], acc[mt][nt][3]);
#pragma unroll
                for (int q = 0; q < 4; q++) {
                    float v = acc[mt][nt][q];
                    s[mt] += v; s2[mt] += v * v;
                }
            }
        }
#pragma unroll
        for (int mt = 0; mt < 4; mt++) {
#pragma unroll
            for (int off = 16; off > 0; off >>= 1) {
                s[mt]  += __shfl_down_sync(0xFFFFFFFFu, s[mt], off);
                s2[mt] += __shfl_down_sync(0xFFFFFFFFu, s2[mt], off);
            }
        }
        __syncthreads();
        if (lane == 0) {
#pragma unroll
            for (int mt = 0; mt < 4; mt++) {
                sred[w][mt][0] = s[mt];
                sred[w][mt][1] = s2[mt];
            }
        }
        __syncthreads();
        if (tid < 8) {
            const int twm = tid >> 2, tmt = tid & 3;
            float S = 0.f, S2 = 0.f;
#pragma unroll
            for (int j = 0; j < 4; j++) {
                S  += sred[twm + 2 * j][tmt][0];
                S2 += sred[twm + 2 * j][tmt][1];
            }
            const int g = blockIdx.y * 8 + twm * 4 + tmt;
            const int ng = blockIdx.z * G_ + g;
            partials[ng * NBLK + blockIdx.x] = S;
            partials[N_ * G_ * NBLK + ng * NBLK + blockIdx.x] = S2;
        }
    } else {
        const float* fn = fusedsrc + (size_t)blockIdx.z * CHW;
#pragma unroll
        for (int mt = 0; mt < 4; mt++) {
            const int r0 = m0 + wm * 64 + mt * 16 + (lane >> 2);
#pragma unroll
            for (int nt = 0; nt < 4; nt++) {
                const int cc = n0 + wn * 32 + nt * 8 + (lane & 3) * 2;
#pragma unroll
                for (int half = 0; half < 2; half++) {
                    const int r = r0 + half * 8;
                    const float bg = b_gate[r];
                    float2 fv = *(const float2*)(fn + (size_t)r * HW + cc);
                    float g0 = 1.f / (1.f + expf(-(acc[mt][nt][half * 2 + 0] + bg)));
                    float g1 = 1.f / (1.f + expf(-(acc[mt][nt][half * 2 + 1] + bg)));
                    *(float2*)(Yn + (size_t)r * HW + cc) =
                        make_float2(fv.x * g0, fv.y * g1);
                }
            }
        }
    }
}

// ---------------------------------------------------------------------------
// fp32 -> fp16 (vectorized)
// ---------------------------------------------------------------------------
__global__ void cvt_x_k(const float* __restrict__ in, __half* __restrict__ o, int n4) {
    int i = blockIdx.x * 256 + threadIdx.x;
    if (i >= n4) return;
    float4 v = *(const float4*)(in + i * 4);
    __half2 a(__float2half(v.x), __float2half(v.y));
    __half2 b(__float2half(v.z), __float2half(v.w));
    uint2 pk = make_uint2(*(uint32_t*)&a, *(uint32_t*)&b);
    *(uint2*)(o + i * 4) = pk;
}

// ---------------------------------------------------------------------------
__global__ void finalize_stats_k(const float* __restrict__ partials,
                                 float* __restrict__ stats) {
    const int ng = threadIdx.x;
    float s = 0.f, s2 = 0.f;
    for (int b = 0; b < NBLK; b++) {
        s  += partials[ng * NBLK + b];
        s2 += partials[N_ * G_ * NBLK + ng * NBLK + b];
    }
    const float M = (float)(CPG * HW);
    float mean = s / M;
    float var = s2 / M - mean * mean;
    stats[ng * 2] = mean;
    stats[ng * 2 + 1] = rsqrtf(var + EPSV);
}

// ---------------------------------------------------------------------------
// GN + SiLU + fused. h written fp16 (GEMM operand), fused fp32.
// ---------------------------------------------------------------------------
__global__ void gn_silu_rowcol_k(const float* __restrict__ X,
                                 const float* __restrict__ stats,
                                 const float* __restrict__ gamma,
                                 const float* __restrict__ beta,
                                 __half* __restrict__ Hh,
                                 float* __restrict__ F) {
    __shared__ float plane[HW];
    __shared__ float rs[H_], cs[W_];
    const int nc = blockIdx.x;
    const int c = nc & (C_ - 1);
    const int ng = (nc >> 8) * G_ + (c >> 4);
    const float mean = stats[ng * 2];
    const float rstd = stats[ng * 2 + 1];
    const float ga = gamma[c];
    const float be = beta[c];
    const float* base = X + (size_t)nc * HW;
    __half* hh = Hh + (size_t)nc * HW;
    float* fb = F + (size_t)nc * HW;

    for (int i = threadIdx.x; i < HW; i += 256) {
        float v = base[i];
        v = (v - mean) * rstd * ga + be;
        float sg = 1.f / (1.f + expf(-v));
        v = v * sg;
        plane[i] = v;
        hh[i] = __float2half(v);
    }
    __syncthreads();
    if (threadIdx.x < H_) {
        const int y = threadIdx.x;
        float s = 0.f;
#pragma unroll 8
        for (int x = 0; x < W_; x++) s += plane[y * W_ + x];
        rs[y] = s;
    } else if (threadIdx.x < H_ + W_) {
        const int x = threadIdx.x - H_;
        float s = 0.f;
#pragma unroll 8
        for (int y = 0; y < H_; y++) s += plane[y * W_ + x];
        cs[x] = s;
    }
    __syncthreads();
    for (int i = threadIdx.x; i < HW; i += 256) {
        const int y = i / W_;
        const int x = i - y * W_;
        fb[i] = 0.25f * (rs[y] + cs[x] + 2.f * plane[i]);
    }
}

// ---------------------------------------------------------------------------
// depthwise 3x3 — plane in smem; output fp16 (GEMM operand)
// ---------------------------------------------------------------------------
__global__ void dw3x3_k(const float* __restrict__ in,
                        const float* __restrict__ wdw,
                        __half* __restrict__ Oh) {
    __shared__ float pl[HW];
    const int nc = blockIdx.x;
    const int c = nc & (C_ - 1);
    float wr[9];
#pragma unroll
    for (int q = 0; q < 9; q++) wr[q] = __ldg(wdw + c * 9 + q);
    const float* p = in + (size_t)nc * HW;
    __half* oh = Oh + (size_t)nc * HW;
    for (int i = threadIdx.x; i < HW; i += 256) pl[i] = p[i];
    __syncthreads();
    for (int i = threadIdx.x; i < HW; i += 256) {
        const int y = i / W_;
        const int x = i - y * W_;
        float s = 0.f;
#pragma unroll
        for (int dy = -1; dy <= 1; dy++) {
            const int yy = y + dy;
            if ((unsigned)yy >= H_) continue;
#pragma unroll
            for (int dx = -1; dx <= 1; dx++) {
                const int xx = x + dx;
                if ((unsigned)xx >= W_) continue;
                s += wr[(dy + 1) * 3 + (dx + 1)] * pl[yy * W_ + xx];
            }
        }
        oh[i] = __float2half(s);
    }
}

// ---------------------------------------------------------------------------
__global__ void gn_silu_out_k(const float* __restrict__ X,
                              const float* __restrict__ stats,
                              const float* __restrict__ gamma,
                              const float* __restrict__ beta,
                              float* __restrict__ out) {
    const int idx = blockIdx.x * 256 + threadIdx.x;
    const int nc = idx / HW;
    const int c = nc & (C_ - 1);
    const int ng = (nc >> 8) * G_ + (c >> 4);
    float v = X[idx];
    v = (v - stats[ng * 2]) * stats[ng * 2 + 1] * gamma[c] + beta[c];
    float sg = 1.f / (1.f + expf(-v));
    out[idx] = v * sg;
}

// ---------------------------------------------------------------------------
extern "C" void kernel_launch(void* const* d_in, const int* in_sizes, int n_in,
                              void* d_out, int out_size) {
    const float* x      = (const float*)d_in[0];
    const float* w_pre  = (const float*)d_in[1];
    const float* g1     = (const float*)d_in[2];
    const float* b1     = (const float*)d_in[3];
    const float* w_gate = (const float*)d_in[4];
    const float* b_gate = (const float*)d_in[5];
    const float* w_dw   = (const float*)d_in[6];
    const float* w_pw   = (const float*)d_in[7];
    const float* g2     = (const float*)d_in[8];
    const float* b2     = (const float*)d_in[9];
    float* out = (float*)d_out;

    float *buf1, *buf2, *buf3, *stats1, *stats2, *partials;
    __half *xh, *hh, *dh, *wh;
    cudaGetSymbolAddress((void**)&buf1, g_buf1);
    cudaGetSymbolAddress((void**)&buf2, g_buf2);
    cudaGetSymbolAddress((void**)&buf3, g_buf3);
    cudaGetSymbolAddress((void**)&stats1, g_stats1);
    cudaGetSymbolAddress((void**)&stats2, g_stats2);
    cudaGetSymbolAddress((void**)&partials, g_partials);
    cudaGetSymbolAddress((void**)&xh, g_xh);
    cudaGetSymbolAddress((void**)&hh, g_hh);
    cudaGetSymbolAddress((void**)&dh, g_dh);
    cudaGetSymbolAddress((void**)&wh, g_wh);

    cudaFuncSetAttribute(gemm_mma<0>, cudaFuncAttributeMaxDynamicSharedMemorySize, GEMM_SMEM);
    cudaFuncSetAttribute(gemm_mma<1>, cudaFuncAttributeMaxDynamicSharedMemorySize, GEMM_SMEM);

    dim3 ggrid(NBLK, 2, N_);
    const int eblocks = NCHW / 256;

    // 0) operand conversion
    cvt_x_k<<<C_*C_/4/256, 256>>>(w_pre,  wh,           C_*C_/4);
    cvt_x_k<<<C_*C_/4/256, 256>>>(w_gate, wh + C_*C_,   C_*C_/4);
    cvt_x_k<<<C_*C_/4/256, 256>>>(w_pw,   wh + 2*C_*C_, C_*C_/4);
    cvt_x_k<<<NCHW/4/256, 256>>>(x, xh, NCHW/4);

    // 1) h0 = conv1x1(x, w_pre) + GN1 partial stats
    gemm_mma<0><<<ggrid, 256, GEMM_SMEM>>>(wh, xh, buf1, partials, nullptr, nullptr);
    finalize_stats_k<<<1, 128>>>(partials, stats1);
    // 2) h = silu(gn(h0)) -> fp16 + fused -> buf2
    gn_silu_rowcol_k<<<N_ * C_, 256>>>(buf1, stats1, g1, b1, hh, buf2);
    // 3) gated = fused * sigmoid(conv1x1(h,w_gate)+b) -> buf3
    gemm_mma<1><<<ggrid, 256, GEMM_SMEM>>>(wh + C_*C_, hh, buf3, nullptr, buf2, b_gate);
    // 4) depthwise 3x3: buf3 -> fp16
    dw3x3_k<<<N_ * C_, 256>>>(buf3, w_dw, dh);
    // 5) y = conv1x1(dw, w_pw) + GN2 partial stats
    gemm_mma<0><<<ggrid, 256, GEMM_SMEM>>>(wh + 2*C_*C_, dh, buf1, partials, nullptr, nullptr);
    finalize_stats_k<<<1, 128>>>(partials, stats2);
    // 6) out = silu(gn(y))
    gn_silu_out_k<<<eblocks, 256>>>(buf1, stats2, g2, b2, out);
}

// round 9
// speedup vs baseline: 3.1545x; 1.1341x over previous
#include <cuda_runtime.h>
#include <cuda_fp16.h>
#include <math.h>
#include <cstdint>

#define C_ 256
#define G_ 16
#define CPG 16
#define N_ 8
#define H_ 80
#define W_ 80
#define HW 6400
#define CHW (C_*HW)
#define NCHW (N_*C_*HW)
#define EPSV 1e-5f
#define NBLK 50   // grid.x of gemm (HW/128)

// fp16 tensor planes
__device__ __half g_xh[NCHW];    // x fp16          (gemm1 B)
__device__ __half g_h0[NCHW];    // gemm1 out
__device__ __half g_hh[NCHW];    // h = silu(gn(h0)) (gemm2 B)
__device__ __half g_fu[NCHW];    // fused
__device__ __half g_gt[NCHW];    // gated
__device__ __half g_dh[NCHW];    // dw out           (gemm3 B)
__device__ __half g_y[NCHW];     // gemm3 out
__device__ __half g_wh[3*C_*C_]; // weights fp16
// fp32 small scratch
__device__ float g_stats1[N_*G_*2];
__device__ float g_stats2[N_*G_*2];
__device__ float g_partials[2 * N_ * G_ * NBLK];

__device__ __forceinline__ uint32_t smem_u32(const void* p) {
    uint32_t a;
    asm("{ .reg .u64 t; cvta.to.shared.u64 t, %1; cvt.u32.u64 %0, t; }"
        : "=r"(a) : "l"(p));
    return a;
}
#define CP_ASYNC16(dst, src) \
    asm volatile("cp.async.cg.shared.global [%0], [%1], 16;" :: "r"(dst), "l"(src))
#define CP_COMMIT() asm volatile("cp.async.commit_group;" ::: "memory")
#define CP_WAIT(n)  asm volatile("cp.async.wait_group %0;" :: "n"(n) : "memory")

// ===========================================================================
// smem: A resident [128 x 264 halfs] = 67584 B, B ring 3 x [32 x 136 halfs]
// ===========================================================================
#define A_STRIDE 264
#define A_BYTES  (128*A_STRIDE*2)
#define B_STRIDE 136
#define B_STAGE  (32*B_STRIDE*2)
#define NSTAGE   3
#define GEMM_SMEM (A_BYTES + NSTAGE*B_STAGE)

__device__ __forceinline__ void ldsm_x4(uint32_t* r, uint32_t addr) {
    asm volatile("ldmatrix.sync.aligned.m8n8.x4.shared.b16 {%0,%1,%2,%3}, [%4];"
        : "=r"(r[0]), "=r"(r[1]), "=r"(r[2]), "=r"(r[3]) : "r"(addr));
}
__device__ __forceinline__ void ldsm_x2t(uint32_t* r, uint32_t addr) {
    asm volatile("ldmatrix.sync.aligned.m8n8.x2.trans.shared.b16 {%0,%1}, [%2];"
        : "=r"(r[0]), "=r"(r[1]) : "r"(addr));
}
__device__ __forceinline__ void mma_f16(float* c, const uint32_t* a, const uint32_t* b) {
    asm volatile(
        "mma.sync.aligned.m16n8k16.row.col.f32.f16.f16.f32 "
        "{%0,%1,%2,%3}, {%4,%5,%6,%7}, {%8,%9}, {%0,%1,%2,%3};"
        : "+f"(c[0]), "+f"(c[1]), "+f"(c[2]), "+f"(c[3])
        : "r"(a[0]), "r"(a[1]), "r"(a[2]), "r"(a[3]), "r"(b[0]), "r"(b[1]));
}
__device__ __forceinline__ float sigm(float v) {
    return 1.f / (1.f + __expf(-v));
}

__device__ __forceinline__ void issue_b(uint32_t sbase, int tid, int k0, int n0,
                                        const __half* Bx) {
#pragma unroll
    for (int j = 0; j < 2; j++) {
        int i = tid + 256 * j;
        int kk = i >> 4, seg = i & 15;
        uint32_t dst = sbase + (uint32_t)(kk * (B_STRIDE * 2) + seg * 16);
        CP_ASYNC16(dst, Bx + (size_t)(k0 + kk) * HW + n0 + seg * 8);
    }
}

template<int MODE>
__global__ __launch_bounds__(256, 2)
void gemm_mma(const __half* __restrict__ Wh, const __half* __restrict__ Bx,
              __half* __restrict__ Y,
              float* __restrict__ partials,
              const __half* __restrict__ fusedsrc,
              const float* __restrict__ b_gate) {
    extern __shared__ char smem[];
    __shared__ float sred[8][4][2];
    const uint32_t sb = smem_u32(smem);
    const uint32_t bb = sb + A_BYTES;
    const int tid = threadIdx.x;
    const int lane = tid & 31;
    const int w = tid >> 5;
    const int wm = w & 1;
    const int wn = w >> 1;
    const int n0 = blockIdx.x * 128;
    const int m0 = blockIdx.y * 128;
    const __half* Bn = Bx + (size_t)blockIdx.z * CHW;
    __half* Yn = Y + (size_t)blockIdx.z * CHW;

    float acc[4][4][4];
#pragma unroll
    for (int i = 0; i < 4; i++)
#pragma unroll
        for (int j = 0; j < 4; j++)
#pragma unroll
            for (int q = 0; q < 4; q++) acc[i][j][q] = 0.f;

#pragma unroll
    for (int j = 0; j < 16; j++) {
        int i = tid + 256 * j;
        int row = i >> 5, seg = i & 31;
        uint32_t dst = sb + (uint32_t)(row * (A_STRIDE * 2) + seg * 16);
        CP_ASYNC16(dst, Wh + (size_t)(m0 + row) * 256 + seg * 8);
    }
    issue_b(bb, tid, 0, n0, Bn);
    CP_COMMIT();
    issue_b(bb + B_STAGE, tid, 32, n0, Bn);
    CP_COMMIT();

    const uint32_t a_lane_off = (uint32_t)((lane & 15) * A_STRIDE + ((lane >> 4) << 3)) * 2;
    const uint32_t b_lane_off = (uint32_t)((lane & 15) * B_STRIDE) * 2;

    for (int ch = 0; ch < 8; ch++) {
        const int st = ch % NSTAGE;
        if (ch < 7) { CP_WAIT(1); } else { CP_WAIT(0); }
        __syncthreads();
        {
            const uint32_t a_chunk = sb + (uint32_t)(wm * 64) * (A_STRIDE * 2)
                                     + a_lane_off + (uint32_t)(ch * 32) * 2;
            const uint32_t SBB = bb + st * B_STAGE;
#pragma unroll
            for (int ks = 0; ks < 2; ks++) {
                const uint32_t kb = (uint32_t)(ks * 16);
                uint32_t ah[4][4], bh[4][2];
#pragma unroll
                for (int mt = 0; mt < 4; mt++) {
                    ldsm_x4(ah[mt], a_chunk + (uint32_t)(mt * 16) * (A_STRIDE * 2) + kb * 2);
                }
#pragma unroll
                for (int nt = 0; nt < 4; nt++) {
                    ldsm_x2t(bh[nt], SBB + b_lane_off + kb * (B_STRIDE * 2)
                                     + (uint32_t)(wn * 32 + nt * 8) * 2);
                }
#pragma unroll
                for (int mt = 0; mt < 4; mt++)
#pragma unroll
                    for (int nt = 0; nt < 4; nt++)
                        mma_f16(acc[mt][nt], ah[mt], bh[nt]);
            }
        }
        if (ch < 6) {
            issue_b(bb + ((ch + 2) % NSTAGE) * B_STAGE, tid, (ch + 2) * 32, n0, Bn);
            CP_COMMIT();
        }
    }

    if (MODE == 0) {
        // store fp16 + per-group partial stats (stats from fp32 accs)
        float s[4], s2[4];
#pragma unroll
        for (int mt = 0; mt < 4; mt++) { s[mt] = 0.f; s2[mt] = 0.f; }
#pragma unroll
        for (int mt = 0; mt < 4; mt++) {
            const int r = m0 + wm * 64 + mt * 16 + (lane >> 2);
#pragma unroll
            for (int nt = 0; nt < 4; nt++) {
                const int cc = n0 + wn * 32 + nt * 8 + (lane & 3) * 2;
                __half2 p01 = __floats2half2_rn(acc[mt][nt][0], acc[mt][nt][1]);
                __half2 p23 = __floats2half2_rn(acc[mt][nt][2], acc[mt][nt][3]);
                *(__half2*)(Yn + (size_t)r * HW + cc) = p01;
                *(__half2*)(Yn + (size_t)(r + 8) * HW + cc) = p23;
#pragma unroll
                for (int q = 0; q < 4; q++) {
                    float v = acc[mt][nt][q];
                    s[mt] += v; s2[mt] += v * v;
                }
            }
        }
#pragma unroll
        for (int mt = 0; mt < 4; mt++) {
#pragma unroll
            for (int off = 16; off > 0; off >>= 1) {
                s[mt]  += __shfl_down_sync(0xFFFFFFFFu, s[mt], off);
                s2[mt] += __shfl_down_sync(0xFFFFFFFFu, s2[mt], off);
            }
        }
        __syncthreads();
        if (lane == 0) {
#pragma unroll
            for (int mt = 0; mt < 4; mt++) {
                sred[w][mt][0] = s[mt];
                sred[w][mt][1] = s2[mt];
            }
        }
        __syncthreads();
        if (tid < 8) {
            const int twm = tid >> 2, tmt = tid & 3;
            float S = 0.f, S2 = 0.f;
#pragma unroll
            for (int j = 0; j < 4; j++) {
                S  += sred[twm + 2 * j][tmt][0];
                S2 += sred[twm + 2 * j][tmt][1];
            }
            const int g = blockIdx.y * 8 + twm * 4 + tmt;
            const int ng = blockIdx.z * G_ + g;
            partials[ng * NBLK + blockIdx.x] = S;
            partials[N_ * G_ * NBLK + ng * NBLK + blockIdx.x] = S2;
        }
    } else {
        // gated epilogue: Y = fused * sigmoid(acc + b_gate)
        const __half* fn = fusedsrc + (size_t)blockIdx.z * CHW;
#pragma unroll
        for (int mt = 0; mt < 4; mt++) {
            const int r0 = m0 + wm * 64 + mt * 16 + (lane >> 2);
#pragma unroll
            for (int nt = 0; nt < 4; nt++) {
                const int cc = n0 + wn * 32 + nt * 8 + (lane & 3) * 2;
#pragma unroll
                for (int half = 0; half < 2; half++) {
                    const int r = r0 + half * 8;
                    const float bg = b_gate[r];
                    float2 fv = __half22float2(*(const __half2*)(fn + (size_t)r * HW + cc));
                    float o0 = fv.x * sigm(acc[mt][nt][half * 2 + 0] + bg);
                    float o1 = fv.y * sigm(acc[mt][nt][half * 2 + 1] + bg);
                    *(__half2*)(Yn + (size_t)r * HW + cc) = __floats2half2_rn(o0, o1);
                }
            }
        }
    }
}

// ---------------------------------------------------------------------------
// fp32 -> fp16 (vectorized)
// ---------------------------------------------------------------------------
__global__ void cvt_x_k(const float* __restrict__ in, __half* __restrict__ o, int n4) {
    int i = blockIdx.x * 256 + threadIdx.x;
    if (i >= n4) return;
    float4 v = *(const float4*)(in + i * 4);
    __half2 a = __floats2half2_rn(v.x, v.y);
    __half2 b = __floats2half2_rn(v.z, v.w);
    uint2 pk = make_uint2(*(uint32_t*)&a, *(uint32_t*)&b);
    *(uint2*)(o + i * 4) = pk;
}
// 3 weight tensors in one launch (grid.y selects)
__global__ void cvt_w3_k(const float* __restrict__ w0, const float* __restrict__ w1,
                         const float* __restrict__ w2, __half* __restrict__ o) {
    const float* src = (blockIdx.y == 0) ? w0 : (blockIdx.y == 1) ? w1 : w2;
    __half* dst = o + (size_t)blockIdx.y * C_ * C_;
    int i = blockIdx.x * 256 + threadIdx.x;
    float4 v = *(const float4*)(src + i * 4);
    __half2 a = __floats2half2_rn(v.x, v.y);
    __half2 b = __floats2half2_rn(v.z, v.w);
    uint2 pk = make_uint2(*(uint32_t*)&a, *(uint32_t*)&b);
    *(uint2*)(dst + i * 4) = pk;
}

// ---------------------------------------------------------------------------
__global__ void finalize_stats_k(const float* __restrict__ partials,
                                 float* __restrict__ stats) {
    const int ng = threadIdx.x;
    float s = 0.f, s2 = 0.f;
    for (int b = 0; b < NBLK; b++) {
        s  += partials[ng * NBLK + b];
        s2 += partials[N_ * G_ * NBLK + ng * NBLK + b];
    }
    const float M = (float)(CPG * HW);
    float mean = s / M;
    float var = s2 / M - mean * mean;
    stats[ng * 2] = mean;
    stats[ng * 2 + 1] = rsqrtf(var + EPSV);
}

// ---------------------------------------------------------------------------
// GN + SiLU + fused. All fp16 I/O; plane fp32 in smem.
// ---------------------------------------------------------------------------
__global__ void gn_silu_rowcol_k(const __half* __restrict__ H0,
                                 const float* __restrict__ stats,
                                 const float* __restrict__ gamma,
                                 const float* __restrict__ beta,
                                 __half* __restrict__ Hh,
                                 __half* __restrict__ F) {
    __shared__ float plane[HW];
    __shared__ float rs[H_], cs[W_];
    const int nc = blockIdx.x;
    const int c = nc & (C_ - 1);
    const int ng = (nc >> 8) * G_ + (c >> 4);
    const float mean = stats[ng * 2];
    const float rstd = stats[ng * 2 + 1];
    const float ga = gamma[c];
    const float be = beta[c];
    const __half2* base = (const __half2*)(H0 + (size_t)nc * HW);
    __half2* hh = (__half2*)(Hh + (size_t)nc * HW);
    __half2* fb = (__half2*)(F + (size_t)nc * HW);

    for (int i = threadIdx.x; i < HW / 2; i += 256) {
        float2 v = __half22float2(base[i]);
        v.x = (v.x - mean) * rstd * ga + be;
        v.y = (v.y - mean) * rstd * ga + be;
        v.x = v.x * sigm(v.x);
        v.y = v.y * sigm(v.y);
        plane[2 * i] = v.x;
        plane[2 * i + 1] = v.y;
        hh[i] = __floats2half2_rn(v.x, v.y);
    }
    __syncthreads();
    if (threadIdx.x < H_) {
        const int y = threadIdx.x;
        float s = 0.f;
#pragma unroll 8
        for (int x = 0; x < W_; x++) s += plane[y * W_ + x];
        rs[y] = s;
    } else if (threadIdx.x < H_ + W_) {
        const int x = threadIdx.x - H_;
        float s = 0.f;
#pragma unroll 8
        for (int y = 0; y < H_; y++) s += plane[y * W_ + x];
        cs[x] = s;
    }
    __syncthreads();
    for (int i = threadIdx.x; i < HW / 2; i += 256) {
        const int p0 = 2 * i;
        const int y = p0 / W_;
        const int x = p0 - y * W_;   // W_ even -> both elems same row
        float f0 = 0.25f * (rs[y] + cs[x] + 2.f * plane[p0]);
        float f1 = 0.25f * (rs[y] + cs[x + 1] + 2.f * plane[p0 + 1]);
        fb[i] = __floats2half2_rn(f0, f1);
    }
}

// ---------------------------------------------------------------------------
// depthwise 3x3 — fp16 in/out; plane fp32 in smem
// ---------------------------------------------------------------------------
__global__ void dw3x3_k(const __half* __restrict__ in,
                        const float* __restrict__ wdw,
                        __half* __restrict__ Oh) {
    __shared__ float pl[HW];
    const int nc = blockIdx.x;
    const int c = nc & (C_ - 1);
    float wr[9];
#pragma unroll
    for (int q = 0; q < 9; q++) wr[q] = __ldg(wdw + c * 9 + q);
    const __half2* p = (const __half2*)(in + (size_t)nc * HW);
    __half2* oh = (__half2*)(Oh + (size_t)nc * HW);
    for (int i = threadIdx.x; i < HW / 2; i += 256) {
        float2 v = __half22float2(p[i]);
        pl[2 * i] = v.x;
        pl[2 * i + 1] = v.y;
    }
    __syncthreads();
    for (int i = threadIdx.x; i < HW / 2; i += 256) {
        const int p0 = 2 * i;
        const int y = p0 / W_;
        const int x0 = p0 - y * W_;
        float o[2];
#pragma unroll
        for (int e = 0; e < 2; e++) {
            const int x = x0 + e;
            float s = 0.f;
#pragma unroll
            for (int dy = -1; dy <= 1; dy++) {
                const int yy = y + dy;
                if ((unsigned)yy >= H_) continue;
#pragma unroll
                for (int dx = -1; dx <= 1; dx++) {
                    const int xx = x + dx;
                    if ((unsigned)xx >= W_) continue;
                    s += wr[(dy + 1) * 3 + (dx + 1)] * pl[yy * W_ + xx];
                }
            }
            o[e] = s;
        }
        oh[i] = __floats2half2_rn(o[0], o[1]);
    }
}

// ---------------------------------------------------------------------------
// final: out = silu(gn(y)), y fp16 -> out fp32
// ---------------------------------------------------------------------------
__global__ void gn_silu_out_k(const __half* __restrict__ Yin,
                              const float* __restrict__ stats,
                              const float* __restrict__ gamma,
                              const float* __restrict__ beta,
                              float* __restrict__ out) {
    const int i2 = blockIdx.x * 256 + threadIdx.x;   // half2 index
    const int idx = i2 * 2;
    const int nc = idx / HW;
    const int c = nc & (C_ - 1);
    const int ng = (nc >> 8) * G_ + (c >> 4);
    const float mean = stats[ng * 2];
    const float rstd = stats[ng * 2 + 1];
    const float ga = gamma[c];
    const float be = beta[c];
    float2 v = __half22float2(*(const __half2*)(Yin + idx));
    v.x = (v.x - mean) * rstd * ga + be;
    v.y = (v.y - mean) * rstd * ga + be;
    *(float2*)(out + idx) = make_float2(v.x * sigm(v.x), v.y * sigm(v.y));
}

// ---------------------------------------------------------------------------
extern "C" void kernel_launch(void* const* d_in, const int* in_sizes, int n_in,
                              void* d_out, int out_size) {
    const float* x      = (const float*)d_in[0];
    const float* w_pre  = (const float*)d_in[1];
    const float* g1     = (const float*)d_in[2];
    const float* b1     = (const float*)d_in[3];
    const float* w_gate = (const float*)d_in[4];
    const float* b_gate = (const float*)d_in[5];
    const float* w_dw   = (const float*)d_in[6];
    const float* w_pw   = (const float*)d_in[7];
    const float* g2     = (const float*)d_in[8];
    const float* b2     = (const float*)d_in[9];
    float* out = (float*)d_out;

    float *stats1, *stats2, *partials;
    __half *xh, *h0, *hh, *fu, *gt, *dh, *y16, *wh;
    cudaGetSymbolAddress((void**)&stats1, g_stats1);
    cudaGetSymbolAddress((void**)&stats2, g_stats2);
    cudaGetSymbolAddress((void**)&partials, g_partials);
    cudaGetSymbolAddress((void**)&xh, g_xh);
    cudaGetSymbolAddress((void**)&h0, g_h0);
    cudaGetSymbolAddress((void**)&hh, g_hh);
    cudaGetSymbolAddress((void**)&fu, g_fu);
    cudaGetSymbolAddress((void**)&gt, g_gt);
    cudaGetSymbolAddress((void**)&dh, g_dh);
    cudaGetSymbolAddress((void**)&y16, g_y);
    cudaGetSymbolAddress((void**)&wh, g_wh);

    cudaFuncSetAttribute(gemm_mma<0>, cudaFuncAttributeMaxDynamicSharedMemorySize, GEMM_SMEM);
    cudaFuncSetAttribute(gemm_mma<1>, cudaFuncAttributeMaxDynamicSharedMemorySize, GEMM_SMEM);

    dim3 ggrid(NBLK, 2, N_);

    // 0) operand conversion
    cvt_w3_k<<<dim3(C_*C_/4/256, 3), 256>>>(w_pre, w_gate, w_pw, wh);
    cvt_x_k<<<NCHW/4/256, 256>>>(x, xh, NCHW/4);

    // 1) h0 = conv1x1(x, w_pre) [fp16] + GN1 partial stats
    gemm_mma<0><<<ggrid, 256, GEMM_SMEM>>>(wh, xh, h0, partials, nullptr, nullptr);
    finalize_stats_k<<<1, 128>>>(partials, stats1);
    // 2) h = silu(gn(h0)) -> fp16 + fused -> fp16
    gn_silu_rowcol_k<<<N_ * C_, 256>>>(h0, stats1, g1, b1, hh, fu);
    // 3) gated = fused * sigmoid(conv1x1(h,w_gate)+b) -> fp16
    gemm_mma<1><<<ggrid, 256, GEMM_SMEM>>>(wh + C_*C_, hh, gt, nullptr, fu, b_gate);
    // 4) depthwise 3x3 fp16 -> fp16
    dw3x3_k<<<N_ * C_, 256>>>(gt, w_dw, dh);
    // 5) y = conv1x1(dw, w_pw) [fp16] + GN2 partial stats
    gemm_mma<0><<<ggrid, 256, GEMM_SMEM>>>(wh + 2*C_*C_, dh, y16, partials, nullptr, nullptr);
    finalize_stats_k<<<1, 128>>>(partials, stats2);
    // 6) out = silu(gn(y)) -> fp32
    gn_silu_out_k<<<NCHW/2/256, 256>>>(y16, stats2, g2, b2, out);
}